// round 8
// baseline (speedup 1.0000x reference)
#include <cuda_runtime.h>
#include <cuda_bf16.h>
#include <cuda_fp16.h>
#include <stdint.h>
#include <math.h>

// Problem constants (fixed by the dataset)
#define NN 100000      // nodes
#define NE 1600000     // edges
#define NH 4           // heads
#define NEG_SLOPE 0.2f
#define NB 391         // ceil(NN/256)

// ---------------- device scratch ----------------
__device__ __align__(16) __half g_xh[NN * 128];  // projected features, fp16
__device__ float g_as[NN * NH];         // per-node src logits (fp32)
__device__ float g_ad[NN * NH];         // per-node dst logits (fp32)
__device__ int   g_cnt[NN];
__device__ int   g_rowptr[NN];
__device__ int   g_cursor[NN];
__device__ int   g_total;
__device__ int   g_csr_src[NE];
// padded-transposed bf16 weights: [hi | lo], each [256 n][136 k]
__device__ __align__(16) __nv_bfloat16 g_Bpk[2 * 256 * 136];

__device__ __forceinline__ float lrelu(float v) {
    return v > 0.0f ? v : NEG_SLOPE * v;
}

__device__ __forceinline__ uint32_t smem_u32(const void* p) {
    uint32_t a;
    asm("{ .reg .u64 t; cvta.to.shared.u64 t, %1; cvt.u32.u64 %0, t; }" : "=r"(a) : "l"(p));
    return a;
}

#define LDSM4(r0, r1, r2, r3, addr)                                            \
    asm volatile("ldmatrix.sync.aligned.m8n8.x4.shared.b16 {%0,%1,%2,%3}, [%4];" \
                 : "=r"(r0), "=r"(r1), "=r"(r2), "=r"(r3) : "r"(addr))

#define MMA16816(c, a, b)                                                      \
    asm volatile(                                                              \
        "mma.sync.aligned.m16n8k16.row.col.f32.bf16.bf16.f32 "                 \
        "{%0,%1,%2,%3}, {%4,%5,%6,%7}, {%8,%9}, {%0,%1,%2,%3};"                \
        : "+f"((c)[0]), "+f"((c)[1]), "+f"((c)[2]), "+f"((c)[3])               \
        : "r"((a)[0]), "r"((a)[1]), "r"((a)[2]), "r"((a)[3]),                  \
          "r"((b)[0]), "r"((b)[1]))

// ---------------- prep: W/W_res -> transposed, split, padded bf16 ----------------
__global__ void prep_b(const float* __restrict__ W, const float* __restrict__ Wres) {
    int t = blockIdx.x * blockDim.x + threadIdx.x;
    if (t >= 256 * 16) return;
    int n  = t >> 4;
    int kg = (t & 15) * 8;
    const float* Wm = (n < 128) ? W : Wres;
    int col = n & 127;
    unsigned short hi[8], lo[8];
#pragma unroll
    for (int i = 0; i < 8; i++) {
        float a = Wm[(size_t)(kg + i) * 128 + col];
        __nv_bfloat16 h = __float2bfloat16(a);
        __nv_bfloat16 l = __float2bfloat16(a - __bfloat162float(h));
        hi[i] = *(unsigned short*)&h;
        lo[i] = *(unsigned short*)&l;
    }
    *(uint4*)(g_Bpk + (size_t)n * 136 + kg)               = *(uint4*)hi;
    *(uint4*)(g_Bpk + 256 * 136 + (size_t)n * 136 + kg)   = *(uint4*)lo;
}

// ---------------- tensor-core dual GEMM (mma.sync bf16 split) ----------------
#define SM_AH 0u
#define SM_AL 34816u
#define SM_BH 69632u
#define SM_BL 139264u
#define GEMM_SMEM 208896

__global__ void __launch_bounds__(512, 1)
gemm_tc(const float* __restrict__ feat,
        const float* __restrict__ att_src,
        const float* __restrict__ att_dst,
        float* __restrict__ out)
{
    extern __shared__ unsigned char smem[];
    const uint32_t sbase = smem_u32(smem);
    const int tid = threadIdx.x;
    const int row0 = blockIdx.x * 128;

    // copy pre-split B (hi|lo) from L2
    {
        const uint4* s = (const uint4*)g_Bpk;
        uint4* d = (uint4*)(smem + SM_BH);
#pragma unroll
        for (int j = 0; j < 17; j++) d[tid + j * 512] = s[tid + j * 512];
    }
    // load + split-convert A tile (128 rows x 128 k)
#pragma unroll
    for (int j = 0; j < 4; j++) {
        int i = tid + j * 512;
        int r = i >> 4;
        int kg = (i & 15) * 8;
        int gr = row0 + r;
        unsigned short hi[8], lo[8];
        if (gr < NN) {
            float4 v0 = *(const float4*)(feat + (size_t)gr * 128 + kg);
            float4 v1 = *(const float4*)(feat + (size_t)gr * 128 + kg + 4);
            float a[8] = {v0.x, v0.y, v0.z, v0.w, v1.x, v1.y, v1.z, v1.w};
#pragma unroll
            for (int q = 0; q < 8; q++) {
                __nv_bfloat16 h = __float2bfloat16(a[q]);
                __nv_bfloat16 l = __float2bfloat16(a[q] - __bfloat162float(h));
                hi[q] = *(unsigned short*)&h;
                lo[q] = *(unsigned short*)&l;
            }
        } else {
#pragma unroll
            for (int q = 0; q < 8; q++) { hi[q] = 0; lo[q] = 0; }
        }
        *(uint4*)(smem + SM_AH + (size_t)r * 272 + kg * 2) = *(uint4*)hi;
        *(uint4*)(smem + SM_AL + (size_t)r * 272 + kg * 2) = *(uint4*)lo;
    }
    __syncthreads();

    const int lane = tid & 31;
    const int wid = tid >> 5;
    const int wm = wid & 3;
    const int wn = wid >> 2;

    float c[2][8][4];
#pragma unroll
    for (int mi = 0; mi < 2; mi++)
#pragma unroll
        for (int ni = 0; ni < 8; ni++)
#pragma unroll
            for (int q = 0; q < 4; q++) c[mi][ni][q] = 0.f;

    const uint32_t aRow = (uint32_t)(wm * 32 + (lane & 15));
    const uint32_t aKb  = (uint32_t)((lane >> 4) * 16);
    const uint32_t bN   = (uint32_t)(wn * 64 + ((lane >> 4) * 8) + (lane & 7));
    const uint32_t bKb  = (uint32_t)((((lane >> 3) & 1) * 8) * 2);

#pragma unroll
    for (int pass = 0; pass < 3; pass++) {
        const uint32_t aBase = sbase + ((pass == 2) ? SM_AL : SM_AH);
        const uint32_t bBase = sbase + ((pass == 1) ? SM_BL : SM_BH);
        const uint32_t aAddr0 = aBase + aRow * 272 + aKb;
        const uint32_t bAddr0 = bBase + bN * 272 + bKb;
#pragma unroll
        for (int ks = 0; ks < 8; ks++) {
            const uint32_t kb = (uint32_t)(ks * 32);
            uint32_t a[2][4];
            LDSM4(a[0][0], a[0][1], a[0][2], a[0][3], aAddr0 + kb);
            LDSM4(a[1][0], a[1][1], a[1][2], a[1][3], aAddr0 + 16 * 272 + kb);
            uint32_t b[8][2];
#pragma unroll
            for (int nj = 0; nj < 4; nj++) {
                LDSM4(b[2 * nj][0], b[2 * nj][1], b[2 * nj + 1][0], b[2 * nj + 1][1],
                      bAddr0 + (uint32_t)(nj * 16 * 272) + kb);
            }
#pragma unroll
            for (int mi = 0; mi < 2; mi++)
#pragma unroll
                for (int ni = 0; ni < 8; ni++)
                    MMA16816(c[mi][ni], a[mi], b[ni]);
        }
    }

    // ---------------- epilogue ----------------
    const int qlane = lane >> 2;
    const int qcol  = (lane & 3) * 2;

#pragma unroll
    for (int mi = 0; mi < 2; mi++) {
        const int rA = row0 + wm * 32 + mi * 16 + qlane;
        const int rB = rA + 8;
#pragma unroll
        for (int ni = 0; ni < 8; ni++) {
            const int col = wn * 64 + ni * 8 + qcol;
            if (col < 128) {
                // x stored as fp16 (node_agg gathers these rows)
                __half2 pA = __float22half2_rn(make_float2(c[mi][ni][0], c[mi][ni][1]));
                __half2 pB = __float22half2_rn(make_float2(c[mi][ni][2], c[mi][ni][3]));
                if (rA < NN) *(__half2*)(g_xh + (size_t)rA * 128 + col) = pA;
                if (rB < NN) *(__half2*)(g_xh + (size_t)rB * 128 + col) = pB;
            } else {
                if (rA < NN) *(float2*)(out + (size_t)rA * 128 + col - 128) =
                    make_float2(c[mi][ni][0], c[mi][ni][1]);
                if (rB < NN) *(float2*)(out + (size_t)rB * 128 + col - 128) =
                    make_float2(c[mi][ni][2], c[mi][ni][3]);
            }
        }
    }

    // fused attention logits for the x half (wn 0,1 hold cols 0..127), fp32-exact
    if (wn < 2) {
        const int hA = wn * 2;
        const int hB = wn * 2 + 1;
#pragma unroll
        for (int mi = 0; mi < 2; mi++) {
#pragma unroll
            for (int rp = 0; rp < 2; rp++) {
                float sa = 0.f, da = 0.f, sb = 0.f, db = 0.f;
#pragma unroll
                for (int ni = 0; ni < 4; ni++) {
                    const int col = wn * 64 + ni * 8 + qcol;
                    float x0 = c[mi][ni][2 * rp], x1 = c[mi][ni][2 * rp + 1];
                    sa = fmaf(x0, __ldg(att_src + col), sa);
                    sa = fmaf(x1, __ldg(att_src + col + 1), sa);
                    da = fmaf(x0, __ldg(att_dst + col), da);
                    da = fmaf(x1, __ldg(att_dst + col + 1), da);
                }
#pragma unroll
                for (int ni = 4; ni < 8; ni++) {
                    const int col = wn * 64 + ni * 8 + qcol;
                    float x0 = c[mi][ni][2 * rp], x1 = c[mi][ni][2 * rp + 1];
                    sb = fmaf(x0, __ldg(att_src + col), sb);
                    sb = fmaf(x1, __ldg(att_src + col + 1), sb);
                    db = fmaf(x0, __ldg(att_dst + col), db);
                    db = fmaf(x1, __ldg(att_dst + col + 1), db);
                }
                sa += __shfl_xor_sync(0xffffffffu, sa, 1);
                sa += __shfl_xor_sync(0xffffffffu, sa, 2);
                da += __shfl_xor_sync(0xffffffffu, da, 1);
                da += __shfl_xor_sync(0xffffffffu, da, 2);
                sb += __shfl_xor_sync(0xffffffffu, sb, 1);
                sb += __shfl_xor_sync(0xffffffffu, sb, 2);
                db += __shfl_xor_sync(0xffffffffu, db, 1);
                db += __shfl_xor_sync(0xffffffffu, db, 2);
                if ((lane & 3) == 0) {
                    const int r = row0 + wm * 32 + mi * 16 + rp * 8 + qlane;
                    if (r < NN) {
                        g_as[r * NH + hA] = sa;
                        g_ad[r * NH + hA] = da;
                        g_as[r * NH + hB] = sb;
                        g_ad[r * NH + hB] = db;
                    }
                }
            }
        }
    }
}

// ---------------- CSR build ----------------
__global__ void zero_cnt_kernel() {
    int i = blockIdx.x * blockDim.x + threadIdx.x;
    if (i < NN) g_cnt[i] = 0;
    if (i == 0) g_total = 0;
}

__global__ void hist_kernel(const int* __restrict__ dst) {
    int e = blockIdx.x * blockDim.x + threadIdx.x;
    if (e < NE) atomicAdd(&g_cnt[dst[e]], 1);
}

__global__ void alloc_kernel() {
    int i = blockIdx.x * blockDim.x + threadIdx.x;
    if (i >= NN) return;
    int c = g_cnt[i];
    int r = atomicAdd(&g_total, c);
    g_rowptr[i] = r;
    g_cursor[i] = r;
}

__global__ void scatter_kernel(const int* __restrict__ src,
                               const int* __restrict__ dst) {
    int e = blockIdx.x * blockDim.x + threadIdx.x;
    if (e >= NE) return;
    int d = dst[e];
    int pos = atomicAdd(&g_cursor[d], 1);
    g_csr_src[pos] = src[e];
}

// ---------------- node aggregation: half-warp per edge, 4-wide, single pass ----------------
__global__ void __launch_bounds__(256)
node_agg_kernel(float* __restrict__ out)
{
    int d = (blockIdx.x * blockDim.x + threadIdx.x) >> 5;
    int lane = threadIdx.x & 31;
    if (d >= NN) return;
    const int n = g_cnt[d];
    if (n == 0) return;   // out already holds the residual
    const int base = g_rowptr[d];

    const int half = lane >> 4;
    const int l16  = lane & 15;
    const int h    = l16 >> 2;         // features l16*8.. -> head l16/4
    const float adh = g_ad[(size_t)d * NH + h];

    // prefetch the residual row (hidden under the edge loop)
    float4 r0, r1;
    float* o = out + (size_t)d * 128 + l16 * 8;
    if (half == 0) {
        r0 = *(const float4*)o;
        r1 = *(const float4*)(o + 4);
    }

    float acc[8];
#pragma unroll
    for (int q = 0; q < 8; q++) acc[q] = 0.f;
    float den = 0.f;

    const int* cs = g_csr_src + base;
    const __half* xb = g_xh + (size_t)l16 * 8;

    int i = half;
    // 4-wide batch per half-warp (edges i, i+2, i+4, i+6) -> 8 chains per warp
    for (; i + 6 < n; i += 8) {
        int s0 = cs[i], s1 = cs[i + 2], s2 = cs[i + 4], s3 = cs[i + 6];
        float a0 = g_as[(size_t)s0 * NH + h];
        float a1 = g_as[(size_t)s1 * NH + h];
        float a2 = g_as[(size_t)s2 * NH + h];
        float a3 = g_as[(size_t)s3 * NH + h];
        uint4 v0 = *(const uint4*)(xb + (size_t)s0 * 128);
        uint4 v1 = *(const uint4*)(xb + (size_t)s1 * 128);
        uint4 v2 = *(const uint4*)(xb + (size_t)s2 * 128);
        uint4 v3 = *(const uint4*)(xb + (size_t)s3 * 128);
        float p0 = __expf(lrelu(a0 + adh));
        float p1 = __expf(lrelu(a1 + adh));
        float p2 = __expf(lrelu(a2 + adh));
        float p3 = __expf(lrelu(a3 + adh));
        den += (p0 + p1) + (p2 + p3);
        const __half2* b0 = (const __half2*)&v0;
        const __half2* b1 = (const __half2*)&v1;
        const __half2* b2 = (const __half2*)&v2;
        const __half2* b3 = (const __half2*)&v3;
#pragma unroll
        for (int q = 0; q < 4; q++) {
            float2 f0 = __half22float2(b0[q]);
            float2 f1 = __half22float2(b1[q]);
            float2 f2 = __half22float2(b2[q]);
            float2 f3 = __half22float2(b3[q]);
            acc[2 * q]     = fmaf(f0.x, p0, acc[2 * q]);
            acc[2 * q + 1] = fmaf(f0.y, p0, acc[2 * q + 1]);
            acc[2 * q]     = fmaf(f1.x, p1, acc[2 * q]);
            acc[2 * q + 1] = fmaf(f1.y, p1, acc[2 * q + 1]);
            acc[2 * q]     = fmaf(f2.x, p2, acc[2 * q]);
            acc[2 * q + 1] = fmaf(f2.y, p2, acc[2 * q + 1]);
            acc[2 * q]     = fmaf(f3.x, p3, acc[2 * q]);
            acc[2 * q + 1] = fmaf(f3.y, p3, acc[2 * q + 1]);
        }
    }
    // tail: one edge at a time for this half
    for (; i < n; i += 2) {
        int s0 = cs[i];
        float a0 = g_as[(size_t)s0 * NH + h];
        uint4 v0 = *(const uint4*)(xb + (size_t)s0 * 128);
        float p0 = __expf(lrelu(a0 + adh));
        den += p0;
        const __half2* b0 = (const __half2*)&v0;
#pragma unroll
        for (int q = 0; q < 4; q++) {
            float2 f0 = __half22float2(b0[q]);
            acc[2 * q]     = fmaf(f0.x, p0, acc[2 * q]);
            acc[2 * q + 1] = fmaf(f0.y, p0, acc[2 * q + 1]);
        }
    }

    // combine the two halves
#pragma unroll
    for (int q = 0; q < 8; q++)
        acc[q] += __shfl_xor_sync(0xffffffffu, acc[q], 16);
    den += __shfl_xor_sync(0xffffffffu, den, 16);

    if (half == 0) {
        const float inv = 1.0f / den;
        r0.x = fmaf(acc[0], inv, r0.x);
        r0.y = fmaf(acc[1], inv, r0.y);
        r0.z = fmaf(acc[2], inv, r0.z);
        r0.w = fmaf(acc[3], inv, r0.w);
        r1.x = fmaf(acc[4], inv, r1.x);
        r1.y = fmaf(acc[5], inv, r1.y);
        r1.z = fmaf(acc[6], inv, r1.z);
        r1.w = fmaf(acc[7], inv, r1.w);
        *(float4*)o = r0;
        *(float4*)(o + 4) = r1;
    }
}

// ---------------- launch ----------------
extern "C" void kernel_launch(void* const* d_in, const int* in_sizes, int n_in,
                              void* d_out, int out_size)
{
    const float* feat    = (const float*)d_in[0];
    const float* W       = (const float*)d_in[1];
    const float* att_src = (const float*)d_in[2];
    const float* att_dst = (const float*)d_in[3];
    const float* Wres    = (const float*)d_in[4];
    const int*   src     = (const int*)d_in[5];
    const int*   dst     = (const int*)d_in[6];
    float* out = (float*)d_out;

    static cudaStream_t s2 = nullptr;
    static cudaEvent_t evFork = nullptr, evJoin = nullptr;
    if (!s2) {
        cudaFuncSetAttribute(gemm_tc,
                             cudaFuncAttributeMaxDynamicSharedMemorySize,
                             GEMM_SMEM);
        cudaStreamCreateWithFlags(&s2, cudaStreamNonBlocking);
        cudaEventCreateWithFlags(&evFork, cudaEventDisableTiming);
        cudaEventCreateWithFlags(&evJoin, cudaEventDisableTiming);
    }

    // fork: CSR build on s2, prep+GEMM on the main stream
    cudaEventRecord(evFork, 0);
    cudaStreamWaitEvent(s2, evFork, 0);

    zero_cnt_kernel<<<NB, 256, 0, s2>>>();
    hist_kernel<<<(NE + 255) / 256, 256, 0, s2>>>(dst);
    alloc_kernel<<<NB, 256, 0, s2>>>();
    scatter_kernel<<<(NE + 255) / 256, 256, 0, s2>>>(src, dst);
    cudaEventRecord(evJoin, s2);

    prep_b<<<16, 256>>>(W, Wres);
    gemm_tc<<<(NN + 127) / 128, 512, GEMM_SMEM>>>(feat, att_src, att_dst, out);

    // join: aggregation needs both GEMM outputs and the CSR
    cudaStreamWaitEvent(0, evJoin, 0);
    node_agg_kernel<<<(NN * 32 + 255) / 256, 256>>>(out);
}

// round 9
// speedup vs baseline: 1.0332x; 1.0332x over previous
#include <cuda_runtime.h>
#include <cuda_bf16.h>
#include <cuda_fp16.h>
#include <stdint.h>
#include <math.h>

// Problem constants (fixed by the dataset)
#define NN 100000      // nodes
#define NE 1600000     // edges
#define NH 4           // heads
#define NEG_SLOPE 0.2f
#define NB 391         // ceil(NN/256)

// ---------------- device scratch ----------------
__device__ __align__(16) __half g_xh[NN * 128];  // projected features, fp16
__device__ float g_as[NN * NH];         // per-node src logits (fp32)
__device__ float g_ad[NN * NH];         // per-node dst logits (fp32)
__device__ int   g_cnt[NN];
__device__ int   g_rowptr[NN];
__device__ int   g_cursor[NN];
__device__ int   g_total;
__device__ int   g_csr_src[NE];
// padded-transposed bf16 weights: [hi | lo], each [256 n][136 k]
__device__ __align__(16) __nv_bfloat16 g_Bpk[2 * 256 * 136];

__device__ __forceinline__ float lrelu(float v) {
    return v > 0.0f ? v : NEG_SLOPE * v;
}

__device__ __forceinline__ uint32_t smem_u32(const void* p) {
    uint32_t a;
    asm("{ .reg .u64 t; cvta.to.shared.u64 t, %1; cvt.u32.u64 %0, t; }" : "=r"(a) : "l"(p));
    return a;
}

#define LDSM4(r0, r1, r2, r3, addr)                                            \
    asm volatile("ldmatrix.sync.aligned.m8n8.x4.shared.b16 {%0,%1,%2,%3}, [%4];" \
                 : "=r"(r0), "=r"(r1), "=r"(r2), "=r"(r3) : "r"(addr))

#define MMA16816(c, a, b)                                                      \
    asm volatile(                                                              \
        "mma.sync.aligned.m16n8k16.row.col.f32.bf16.bf16.f32 "                 \
        "{%0,%1,%2,%3}, {%4,%5,%6,%7}, {%8,%9}, {%0,%1,%2,%3};"                \
        : "+f"((c)[0]), "+f"((c)[1]), "+f"((c)[2]), "+f"((c)[3])               \
        : "r"((a)[0]), "r"((a)[1]), "r"((a)[2]), "r"((a)[3]),                  \
          "r"((b)[0]), "r"((b)[1]))

// ---------------- prep: W/W_res -> transposed, split, padded bf16 ----------------
__global__ void prep_b(const float* __restrict__ W, const float* __restrict__ Wres) {
    int t = blockIdx.x * blockDim.x + threadIdx.x;
    if (t >= 256 * 16) return;
    int n  = t >> 4;
    int kg = (t & 15) * 8;
    const float* Wm = (n < 128) ? W : Wres;
    int col = n & 127;
    unsigned short hi[8], lo[8];
#pragma unroll
    for (int i = 0; i < 8; i++) {
        float a = Wm[(size_t)(kg + i) * 128 + col];
        __nv_bfloat16 h = __float2bfloat16(a);
        __nv_bfloat16 l = __float2bfloat16(a - __bfloat162float(h));
        hi[i] = *(unsigned short*)&h;
        lo[i] = *(unsigned short*)&l;
    }
    *(uint4*)(g_Bpk + (size_t)n * 136 + kg)               = *(uint4*)hi;
    *(uint4*)(g_Bpk + 256 * 136 + (size_t)n * 136 + kg)   = *(uint4*)lo;
}

// ---------------- tensor-core dual GEMM (mma.sync bf16 split) ----------------
#define SM_AH 0u
#define SM_AL 34816u
#define SM_BH 69632u
#define SM_BL 139264u
#define GEMM_SMEM 208896

__global__ void __launch_bounds__(512, 1)
gemm_tc(const float* __restrict__ feat,
        const float* __restrict__ att_src,
        const float* __restrict__ att_dst,
        float* __restrict__ out)
{
    extern __shared__ unsigned char smem[];
    const uint32_t sbase = smem_u32(smem);
    const int tid = threadIdx.x;
    const int row0 = blockIdx.x * 128;

    // copy pre-split B (hi|lo) from L2
    {
        const uint4* s = (const uint4*)g_Bpk;
        uint4* d = (uint4*)(smem + SM_BH);
#pragma unroll
        for (int j = 0; j < 17; j++) d[tid + j * 512] = s[tid + j * 512];
    }
    // load + split-convert A tile (128 rows x 128 k)
#pragma unroll
    for (int j = 0; j < 4; j++) {
        int i = tid + j * 512;
        int r = i >> 4;
        int kg = (i & 15) * 8;
        int gr = row0 + r;
        unsigned short hi[8], lo[8];
        if (gr < NN) {
            float4 v0 = *(const float4*)(feat + (size_t)gr * 128 + kg);
            float4 v1 = *(const float4*)(feat + (size_t)gr * 128 + kg + 4);
            float a[8] = {v0.x, v0.y, v0.z, v0.w, v1.x, v1.y, v1.z, v1.w};
#pragma unroll
            for (int q = 0; q < 8; q++) {
                __nv_bfloat16 h = __float2bfloat16(a[q]);
                __nv_bfloat16 l = __float2bfloat16(a[q] - __bfloat162float(h));
                hi[q] = *(unsigned short*)&h;
                lo[q] = *(unsigned short*)&l;
            }
        } else {
#pragma unroll
            for (int q = 0; q < 8; q++) { hi[q] = 0; lo[q] = 0; }
        }
        *(uint4*)(smem + SM_AH + (size_t)r * 272 + kg * 2) = *(uint4*)hi;
        *(uint4*)(smem + SM_AL + (size_t)r * 272 + kg * 2) = *(uint4*)lo;
    }
    __syncthreads();

    const int lane = tid & 31;
    const int wid = tid >> 5;
    const int wm = wid & 3;
    const int wn = wid >> 2;

    float c[2][8][4];
#pragma unroll
    for (int mi = 0; mi < 2; mi++)
#pragma unroll
        for (int ni = 0; ni < 8; ni++)
#pragma unroll
            for (int q = 0; q < 4; q++) c[mi][ni][q] = 0.f;

    const uint32_t aRow = (uint32_t)(wm * 32 + (lane & 15));
    const uint32_t aKb  = (uint32_t)((lane >> 4) * 16);
    const uint32_t bN   = (uint32_t)(wn * 64 + ((lane >> 4) * 8) + (lane & 7));
    const uint32_t bKb  = (uint32_t)((((lane >> 3) & 1) * 8) * 2);

#pragma unroll
    for (int pass = 0; pass < 3; pass++) {
        const uint32_t aBase = sbase + ((pass == 2) ? SM_AL : SM_AH);
        const uint32_t bBase = sbase + ((pass == 1) ? SM_BL : SM_BH);
        const uint32_t aAddr0 = aBase + aRow * 272 + aKb;
        const uint32_t bAddr0 = bBase + bN * 272 + bKb;
#pragma unroll
        for (int ks = 0; ks < 8; ks++) {
            const uint32_t kb = (uint32_t)(ks * 32);
            uint32_t a[2][4];
            LDSM4(a[0][0], a[0][1], a[0][2], a[0][3], aAddr0 + kb);
            LDSM4(a[1][0], a[1][1], a[1][2], a[1][3], aAddr0 + 16 * 272 + kb);
            uint32_t b[8][2];
#pragma unroll
            for (int nj = 0; nj < 4; nj++) {
                LDSM4(b[2 * nj][0], b[2 * nj][1], b[2 * nj + 1][0], b[2 * nj + 1][1],
                      bAddr0 + (uint32_t)(nj * 16 * 272) + kb);
            }
#pragma unroll
            for (int mi = 0; mi < 2; mi++)
#pragma unroll
                for (int ni = 0; ni < 8; ni++)
                    MMA16816(c[mi][ni], a[mi], b[ni]);
        }
    }

    // ---------------- epilogue ----------------
    const int qlane = lane >> 2;
    const int qcol  = (lane & 3) * 2;

#pragma unroll
    for (int mi = 0; mi < 2; mi++) {
        const int rA = row0 + wm * 32 + mi * 16 + qlane;
        const int rB = rA + 8;
#pragma unroll
        for (int ni = 0; ni < 8; ni++) {
            const int col = wn * 64 + ni * 8 + qcol;
            if (col < 128) {
                // x stored as fp16 (node_agg gathers these rows)
                __half2 pA = __float22half2_rn(make_float2(c[mi][ni][0], c[mi][ni][1]));
                __half2 pB = __float22half2_rn(make_float2(c[mi][ni][2], c[mi][ni][3]));
                if (rA < NN) *(__half2*)(g_xh + (size_t)rA * 128 + col) = pA;
                if (rB < NN) *(__half2*)(g_xh + (size_t)rB * 128 + col) = pB;
            } else {
                if (rA < NN) *(float2*)(out + (size_t)rA * 128 + col - 128) =
                    make_float2(c[mi][ni][0], c[mi][ni][1]);
                if (rB < NN) *(float2*)(out + (size_t)rB * 128 + col - 128) =
                    make_float2(c[mi][ni][2], c[mi][ni][3]);
            }
        }
    }

    // fused attention logits for the x half (wn 0,1 hold cols 0..127), fp32-exact
    if (wn < 2) {
        const int hA = wn * 2;
        const int hB = wn * 2 + 1;
#pragma unroll
        for (int mi = 0; mi < 2; mi++) {
#pragma unroll
            for (int rp = 0; rp < 2; rp++) {
                float sa = 0.f, da = 0.f, sb = 0.f, db = 0.f;
#pragma unroll
                for (int ni = 0; ni < 4; ni++) {
                    const int col = wn * 64 + ni * 8 + qcol;
                    float x0 = c[mi][ni][2 * rp], x1 = c[mi][ni][2 * rp + 1];
                    sa = fmaf(x0, __ldg(att_src + col), sa);
                    sa = fmaf(x1, __ldg(att_src + col + 1), sa);
                    da = fmaf(x0, __ldg(att_dst + col), da);
                    da = fmaf(x1, __ldg(att_dst + col + 1), da);
                }
#pragma unroll
                for (int ni = 4; ni < 8; ni++) {
                    const int col = wn * 64 + ni * 8 + qcol;
                    float x0 = c[mi][ni][2 * rp], x1 = c[mi][ni][2 * rp + 1];
                    sb = fmaf(x0, __ldg(att_src + col), sb);
                    sb = fmaf(x1, __ldg(att_src + col + 1), sb);
                    db = fmaf(x0, __ldg(att_dst + col), db);
                    db = fmaf(x1, __ldg(att_dst + col + 1), db);
                }
                sa += __shfl_xor_sync(0xffffffffu, sa, 1);
                sa += __shfl_xor_sync(0xffffffffu, sa, 2);
                da += __shfl_xor_sync(0xffffffffu, da, 1);
                da += __shfl_xor_sync(0xffffffffu, da, 2);
                sb += __shfl_xor_sync(0xffffffffu, sb, 1);
                sb += __shfl_xor_sync(0xffffffffu, sb, 2);
                db += __shfl_xor_sync(0xffffffffu, db, 1);
                db += __shfl_xor_sync(0xffffffffu, db, 2);
                if ((lane & 3) == 0) {
                    const int r = row0 + wm * 32 + mi * 16 + rp * 8 + qlane;
                    if (r < NN) {
                        g_as[r * NH + hA] = sa;
                        g_ad[r * NH + hA] = da;
                        g_as[r * NH + hB] = sb;
                        g_ad[r * NH + hB] = db;
                    }
                }
            }
        }
    }
}

// ---------------- CSR build ----------------
__global__ void zero_cnt_kernel() {
    int i = blockIdx.x * blockDim.x + threadIdx.x;
    if (i < NN) g_cnt[i] = 0;
    if (i == 0) g_total = 0;
}

__global__ void hist_kernel(const int* __restrict__ dst) {
    int e = blockIdx.x * blockDim.x + threadIdx.x;
    if (e < NE) atomicAdd(&g_cnt[dst[e]], 1);
}

__global__ void alloc_kernel() {
    int i = blockIdx.x * blockDim.x + threadIdx.x;
    if (i >= NN) return;
    int c = g_cnt[i];
    int r = atomicAdd(&g_total, c);
    g_rowptr[i] = r;
    g_cursor[i] = r;
}

__global__ void scatter_kernel(const int* __restrict__ src,
                               const int* __restrict__ dst) {
    int e = blockIdx.x * blockDim.x + threadIdx.x;
    if (e >= NE) return;
    int d = dst[e];
    int pos = atomicAdd(&g_cursor[d], 1);
    g_csr_src[pos] = src[e];
}

// ---------------- node aggregation: half-warp per edge, 2-wide, single pass ----------------
__global__ void __launch_bounds__(256)
node_agg_kernel(float* __restrict__ out)
{
    int d = (blockIdx.x * blockDim.x + threadIdx.x) >> 5;
    int lane = threadIdx.x & 31;
    if (d >= NN) return;
    const int n = g_cnt[d];
    if (n == 0) return;   // out already holds the residual
    const int base = g_rowptr[d];

    const int half = lane >> 4;
    const int l16  = lane & 15;
    const int h    = l16 >> 2;         // features l16*8.. -> head l16/4
    const float adh = g_ad[(size_t)d * NH + h];

    float acc[8];
#pragma unroll
    for (int q = 0; q < 8; q++) acc[q] = 0.f;
    float den = 0.f;

    const int* cs = g_csr_src + base;
    const __half* xb = g_xh + (size_t)l16 * 8;

    int i = half;
    // 2-wide batch per half-warp (edges i, i+2)
    for (; i + 2 < n; i += 4) {
        int s0 = cs[i], s1 = cs[i + 2];
        float a0 = g_as[(size_t)s0 * NH + h];
        float a1 = g_as[(size_t)s1 * NH + h];
        uint4 v0 = *(const uint4*)(xb + (size_t)s0 * 128);
        uint4 v1 = *(const uint4*)(xb + (size_t)s1 * 128);
        float p0 = __expf(lrelu(a0 + adh));
        float p1 = __expf(lrelu(a1 + adh));
        den += p0 + p1;
        const __half2* b0 = (const __half2*)&v0;
        const __half2* b1 = (const __half2*)&v1;
#pragma unroll
        for (int q = 0; q < 4; q++) {
            float2 f0 = __half22float2(b0[q]);
            float2 f1 = __half22float2(b1[q]);
            acc[2 * q]     = fmaf(f0.x, p0, acc[2 * q]);
            acc[2 * q + 1] = fmaf(f0.y, p0, acc[2 * q + 1]);
            acc[2 * q]     = fmaf(f1.x, p1, acc[2 * q]);
            acc[2 * q + 1] = fmaf(f1.y, p1, acc[2 * q + 1]);
        }
    }
    if (i < n) {
        int s0 = cs[i];
        float a0 = g_as[(size_t)s0 * NH + h];
        uint4 v0 = *(const uint4*)(xb + (size_t)s0 * 128);
        float p0 = __expf(lrelu(a0 + adh));
        den += p0;
        const __half2* b0 = (const __half2*)&v0;
#pragma unroll
        for (int q = 0; q < 4; q++) {
            float2 f0 = __half22float2(b0[q]);
            acc[2 * q]     = fmaf(f0.x, p0, acc[2 * q]);
            acc[2 * q + 1] = fmaf(f0.y, p0, acc[2 * q + 1]);
        }
    }

    // combine the two halves
#pragma unroll
    for (int q = 0; q < 8; q++)
        acc[q] += __shfl_xor_sync(0xffffffffu, acc[q], 16);
    den += __shfl_xor_sync(0xffffffffu, den, 16);

    if (half == 0) {
        const float inv = 1.0f / den;
        float* o = out + (size_t)d * 128 + l16 * 8;
        float4 r0 = *(const float4*)o;
        float4 r1 = *(const float4*)(o + 4);
        r0.x = fmaf(acc[0], inv, r0.x);
        r0.y = fmaf(acc[1], inv, r0.y);
        r0.z = fmaf(acc[2], inv, r0.z);
        r0.w = fmaf(acc[3], inv, r0.w);
        r1.x = fmaf(acc[4], inv, r1.x);
        r1.y = fmaf(acc[5], inv, r1.y);
        r1.z = fmaf(acc[6], inv, r1.z);
        r1.w = fmaf(acc[7], inv, r1.w);
        *(float4*)o = r0;
        *(float4*)(o + 4) = r1;
    }
}

// ---------------- launch ----------------
extern "C" void kernel_launch(void* const* d_in, const int* in_sizes, int n_in,
                              void* d_out, int out_size)
{
    const float* feat    = (const float*)d_in[0];
    const float* W       = (const float*)d_in[1];
    const float* att_src = (const float*)d_in[2];
    const float* att_dst = (const float*)d_in[3];
    const float* Wres    = (const float*)d_in[4];
    const int*   src     = (const int*)d_in[5];
    const int*   dst     = (const int*)d_in[6];
    float* out = (float*)d_out;

    static cudaStream_t s2 = nullptr;
    static cudaEvent_t evFork = nullptr, evJoin = nullptr;
    if (!s2) {
        cudaFuncSetAttribute(gemm_tc,
                             cudaFuncAttributeMaxDynamicSharedMemorySize,
                             GEMM_SMEM);
        cudaStreamCreateWithFlags(&s2, cudaStreamNonBlocking);
        cudaEventCreateWithFlags(&evFork, cudaEventDisableTiming);
        cudaEventCreateWithFlags(&evJoin, cudaEventDisableTiming);
    }

    // fork: CSR build on s2, prep+GEMM on the main stream.
    // Enqueue order puts gemm_tc 4th (profiler targeting); stream/event
    // dependencies are unchanged.
    cudaEventRecord(evFork, 0);
    cudaStreamWaitEvent(s2, evFork, 0);

    zero_cnt_kernel<<<NB, 256, 0, s2>>>();                       // 1
    hist_kernel<<<(NE + 255) / 256, 256, 0, s2>>>(dst);          // 2
    prep_b<<<16, 256>>>(W, Wres);                                // 3
    gemm_tc<<<(NN + 127) / 128, 512, GEMM_SMEM>>>(feat, att_src, att_dst, out); // 4
    alloc_kernel<<<NB, 256, 0, s2>>>();                          // 5
    scatter_kernel<<<(NE + 255) / 256, 256, 0, s2>>>(src, dst);  // 6
    cudaEventRecord(evJoin, s2);

    // join: aggregation needs both GEMM outputs and the CSR
    cudaStreamWaitEvent(0, evJoin, 0);
    node_agg_kernel<<<(NN * 32 + 255) / 256, 256>>>(out);        // 7
}

// round 10
// speedup vs baseline: 1.0528x; 1.0190x over previous
#include <cuda_runtime.h>
#include <cuda_bf16.h>
#include <cuda_fp16.h>
#include <stdint.h>
#include <math.h>

// Problem constants (fixed by the dataset)
#define NN 100000      // nodes
#define NE 1600000     // edges
#define NH 4           // heads
#define NEG_SLOPE 0.2f
#define NB 391         // ceil(NN/256)

// ---------------- device scratch ----------------
__device__ __align__(16) __half g_xh[NN * 128];  // projected features, fp16
__device__ float g_as[NN * NH];         // per-node src logits (fp32)
__device__ float g_ad[NN * NH];         // per-node dst logits (fp32)
__device__ int   g_cnt[NN];
__device__ int   g_rowptr[NN];
__device__ int   g_cursor[NN];
__device__ int   g_total;
__device__ int   g_csr_src[NE];
// padded-transposed bf16 weights: [hi | lo], each [256 n][136 k]
__device__ __align__(16) __nv_bfloat16 g_Bpk[2 * 256 * 136];

__device__ __forceinline__ float lrelu(float v) {
    return v > 0.0f ? v : NEG_SLOPE * v;
}

__device__ __forceinline__ uint32_t smem_u32(const void* p) {
    uint32_t a;
    asm("{ .reg .u64 t; cvta.to.shared.u64 t, %1; cvt.u32.u64 %0, t; }" : "=r"(a) : "l"(p));
    return a;
}

#define CP_ASYNC16(saddr, gptr)                                                \
    asm volatile("cp.async.cg.shared.global [%0], [%1], 16;"                   \
                 :: "r"(saddr), "l"(gptr))
#define CP_COMMIT() asm volatile("cp.async.commit_group;" ::: "memory")
#define CP_WAIT0()  asm volatile("cp.async.wait_group 0;" ::: "memory")

#define LDSM4(r0, r1, r2, r3, addr)                                            \
    asm volatile("ldmatrix.sync.aligned.m8n8.x4.shared.b16 {%0,%1,%2,%3}, [%4];" \
                 : "=r"(r0), "=r"(r1), "=r"(r2), "=r"(r3) : "r"(addr))

#define MMA16816(c, a, b)                                                      \
    asm volatile(                                                              \
        "mma.sync.aligned.m16n8k16.row.col.f32.bf16.bf16.f32 "                 \
        "{%0,%1,%2,%3}, {%4,%5,%6,%7}, {%8,%9}, {%0,%1,%2,%3};"                \
        : "+f"((c)[0]), "+f"((c)[1]), "+f"((c)[2]), "+f"((c)[3])               \
        : "r"((a)[0]), "r"((a)[1]), "r"((a)[2]), "r"((a)[3]),                  \
          "r"((b)[0]), "r"((b)[1]))

// ---------------- prep: W/W_res -> transposed, split, padded bf16 ----------------
__global__ void prep_b(const float* __restrict__ W, const float* __restrict__ Wres) {
    int t = blockIdx.x * blockDim.x + threadIdx.x;
    if (t >= 256 * 16) return;
    int n  = t >> 4;
    int kg = (t & 15) * 8;
    const float* Wm = (n < 128) ? W : Wres;
    int col = n & 127;
    unsigned short hi[8], lo[8];
#pragma unroll
    for (int i = 0; i < 8; i++) {
        float a = Wm[(size_t)(kg + i) * 128 + col];
        __nv_bfloat16 h = __float2bfloat16(a);
        __nv_bfloat16 l = __float2bfloat16(a - __bfloat162float(h));
        hi[i] = *(unsigned short*)&h;
        lo[i] = *(unsigned short*)&l;
    }
    *(uint4*)(g_Bpk + (size_t)n * 136 + kg)               = *(uint4*)hi;
    *(uint4*)(g_Bpk + 256 * 136 + (size_t)n * 136 + kg)   = *(uint4*)lo;
}

// ---------------- tensor-core dual GEMM (mma.sync bf16 split) ----------------
// SMEM: A_hi [0,34816) A_lo [34816,69632) B_hi [69632,139264) B_lo [139264,208896)
// The A region doubles as a fp32 staging buffer (128 rows x 528B = 67584 B).
#define SM_AH 0u
#define SM_AL 34816u
#define SM_BH 69632u
#define SM_BL 139264u
#define GEMM_SMEM 208896

__global__ void __launch_bounds__(512, 1)
gemm_tc(const float* __restrict__ feat,
        const float* __restrict__ att_src,
        const float* __restrict__ att_dst,
        float* __restrict__ out)
{
    extern __shared__ unsigned char smem[];
    const uint32_t sbase = smem_u32(smem);
    const int tid = threadIdx.x;
    const int row0 = blockIdx.x * 128;

    // ---- async stage: B (hi|lo, 139264 B) + A fp32 (67584 B scratch) ----
    {
        const char* bs = (const char*)g_Bpk;
#pragma unroll
        for (int j = 0; j < 17; j++) {
            uint32_t off = (uint32_t)(tid + j * 512) * 16;
            CP_ASYNC16(sbase + SM_BH + off, bs + off);
        }
#pragma unroll
        for (int j = 0; j < 8; j++) {
            int c = tid + j * 512;       // 4096 16B chunks
            int r = c >> 5;              // 32 chunks per row
            int q = c & 31;
            int gr = row0 + r;
            if (gr >= NN) gr = NN - 1;   // clamp: rows >= NN are discarded later
            CP_ASYNC16(sbase + SM_AH + (uint32_t)(r * 528 + q * 16),
                       (const char*)(feat + (size_t)gr * 128) + q * 16);
        }
        CP_COMMIT();
        CP_WAIT0();
    }
    __syncthreads();

    // ---- convert A: smem fp32 -> regs -> smem bf16 hi/lo (in-place overlay) ----
    {
        float4 st[8];
#pragma unroll
        for (int j = 0; j < 4; j++) {
            int i = tid + j * 512;       // 2048 convert chunks (8 floats each)
            int r = i >> 4;
            int kgB = (i & 15) * 32;
            st[2 * j]     = *(const float4*)(smem + SM_AH + r * 528 + kgB);
            st[2 * j + 1] = *(const float4*)(smem + SM_AH + r * 528 + kgB + 16);
        }
        __syncthreads();                 // all reads done before overwrite
#pragma unroll
        for (int j = 0; j < 4; j++) {
            int i = tid + j * 512;
            int r = i >> 4;
            int kg = (i & 15) * 8;
            float a[8] = {st[2 * j].x, st[2 * j].y, st[2 * j].z, st[2 * j].w,
                          st[2 * j + 1].x, st[2 * j + 1].y, st[2 * j + 1].z, st[2 * j + 1].w};
            unsigned short hi[8], lo[8];
#pragma unroll
            for (int q = 0; q < 8; q++) {
                __nv_bfloat16 h = __float2bfloat16(a[q]);
                __nv_bfloat16 l = __float2bfloat16(a[q] - __bfloat162float(h));
                hi[q] = *(unsigned short*)&h;
                lo[q] = *(unsigned short*)&l;
            }
            *(uint4*)(smem + SM_AH + (size_t)r * 272 + kg * 2) = *(uint4*)hi;
            *(uint4*)(smem + SM_AL + (size_t)r * 272 + kg * 2) = *(uint4*)lo;
        }
    }
    __syncthreads();

    const int lane = tid & 31;
    const int wid = tid >> 5;
    const int wm = wid & 3;
    const int wn = wid >> 2;

    float c[2][8][4];
#pragma unroll
    for (int mi = 0; mi < 2; mi++)
#pragma unroll
        for (int ni = 0; ni < 8; ni++)
#pragma unroll
            for (int q = 0; q < 4; q++) c[mi][ni][q] = 0.f;

    const uint32_t aRow = (uint32_t)(wm * 32 + (lane & 15));
    const uint32_t aKb  = (uint32_t)((lane >> 4) * 16);
    const uint32_t bN   = (uint32_t)(wn * 64 + ((lane >> 4) * 8) + (lane & 7));
    const uint32_t bKb  = (uint32_t)((((lane >> 3) & 1) * 8) * 2);

#pragma unroll
    for (int pass = 0; pass < 3; pass++) {
        const uint32_t aBase = sbase + ((pass == 2) ? SM_AL : SM_AH);
        const uint32_t bBase = sbase + ((pass == 1) ? SM_BL : SM_BH);
        const uint32_t aAddr0 = aBase + aRow * 272 + aKb;
        const uint32_t bAddr0 = bBase + bN * 272 + bKb;
#pragma unroll
        for (int ks = 0; ks < 8; ks++) {
            const uint32_t kb = (uint32_t)(ks * 32);
            uint32_t a[2][4];
            LDSM4(a[0][0], a[0][1], a[0][2], a[0][3], aAddr0 + kb);
            LDSM4(a[1][0], a[1][1], a[1][2], a[1][3], aAddr0 + 16 * 272 + kb);
            uint32_t b[8][2];
#pragma unroll
            for (int nj = 0; nj < 4; nj++) {
                LDSM4(b[2 * nj][0], b[2 * nj][1], b[2 * nj + 1][0], b[2 * nj + 1][1],
                      bAddr0 + (uint32_t)(nj * 16 * 272) + kb);
            }
#pragma unroll
            for (int mi = 0; mi < 2; mi++)
#pragma unroll
                for (int ni = 0; ni < 8; ni++)
                    MMA16816(c[mi][ni], a[mi], b[ni]);
        }
    }

    // ---------------- epilogue ----------------
    const int qlane = lane >> 2;
    const int qcol  = (lane & 3) * 2;

#pragma unroll
    for (int mi = 0; mi < 2; mi++) {
        const int rA = row0 + wm * 32 + mi * 16 + qlane;
        const int rB = rA + 8;
#pragma unroll
        for (int ni = 0; ni < 8; ni++) {
            const int col = wn * 64 + ni * 8 + qcol;
            if (col < 128) {
                // x stored as fp16 (node_agg gathers these rows)
                __half2 pA = __float22half2_rn(make_float2(c[mi][ni][0], c[mi][ni][1]));
                __half2 pB = __float22half2_rn(make_float2(c[mi][ni][2], c[mi][ni][3]));
                if (rA < NN) *(__half2*)(g_xh + (size_t)rA * 128 + col) = pA;
                if (rB < NN) *(__half2*)(g_xh + (size_t)rB * 128 + col) = pB;
            } else {
                if (rA < NN) *(float2*)(out + (size_t)rA * 128 + col - 128) =
                    make_float2(c[mi][ni][0], c[mi][ni][1]);
                if (rB < NN) *(float2*)(out + (size_t)rB * 128 + col - 128) =
                    make_float2(c[mi][ni][2], c[mi][ni][3]);
            }
        }
    }

    // fused attention logits for the x half (wn 0,1 hold cols 0..127), fp32-exact
    if (wn < 2) {
        const int hA = wn * 2;
        const int hB = wn * 2 + 1;
#pragma unroll
        for (int mi = 0; mi < 2; mi++) {
#pragma unroll
            for (int rp = 0; rp < 2; rp++) {
                float sa = 0.f, da = 0.f, sb = 0.f, db = 0.f;
#pragma unroll
                for (int ni = 0; ni < 4; ni++) {
                    const int col = wn * 64 + ni * 8 + qcol;
                    float x0 = c[mi][ni][2 * rp], x1 = c[mi][ni][2 * rp + 1];
                    sa = fmaf(x0, __ldg(att_src + col), sa);
                    sa = fmaf(x1, __ldg(att_src + col + 1), sa);
                    da = fmaf(x0, __ldg(att_dst + col), da);
                    da = fmaf(x1, __ldg(att_dst + col + 1), da);
                }
#pragma unroll
                for (int ni = 4; ni < 8; ni++) {
                    const int col = wn * 64 + ni * 8 + qcol;
                    float x0 = c[mi][ni][2 * rp], x1 = c[mi][ni][2 * rp + 1];
                    sb = fmaf(x0, __ldg(att_src + col), sb);
                    sb = fmaf(x1, __ldg(att_src + col + 1), sb);
                    db = fmaf(x0, __ldg(att_dst + col), db);
                    db = fmaf(x1, __ldg(att_dst + col + 1), db);
                }
                sa += __shfl_xor_sync(0xffffffffu, sa, 1);
                sa += __shfl_xor_sync(0xffffffffu, sa, 2);
                da += __shfl_xor_sync(0xffffffffu, da, 1);
                da += __shfl_xor_sync(0xffffffffu, da, 2);
                sb += __shfl_xor_sync(0xffffffffu, sb, 1);
                sb += __shfl_xor_sync(0xffffffffu, sb, 2);
                db += __shfl_xor_sync(0xffffffffu, db, 1);
                db += __shfl_xor_sync(0xffffffffu, db, 2);
                if ((lane & 3) == 0) {
                    const int r = row0 + wm * 32 + mi * 16 + rp * 8 + qlane;
                    if (r < NN) {
                        g_as[r * NH + hA] = sa;
                        g_ad[r * NH + hA] = da;
                        g_as[r * NH + hB] = sb;
                        g_ad[r * NH + hB] = db;
                    }
                }
            }
        }
    }
}

// ---------------- CSR build ----------------
__global__ void zero_cnt_kernel() {
    int i = blockIdx.x * blockDim.x + threadIdx.x;
    if (i < NN) g_cnt[i] = 0;
    if (i == 0) g_total = 0;
}

__global__ void hist_kernel(const int* __restrict__ dst) {
    int e = blockIdx.x * blockDim.x + threadIdx.x;
    if (e < NE) atomicAdd(&g_cnt[dst[e]], 1);
}

__global__ void alloc_kernel() {
    int i = blockIdx.x * blockDim.x + threadIdx.x;
    if (i >= NN) return;
    int c = g_cnt[i];
    int r = atomicAdd(&g_total, c);
    g_rowptr[i] = r;
    g_cursor[i] = r;
}

__global__ void scatter_kernel(const int* __restrict__ src,
                               const int* __restrict__ dst) {
    int e = blockIdx.x * blockDim.x + threadIdx.x;
    if (e >= NE) return;
    int d = dst[e];
    int pos = atomicAdd(&g_cursor[d], 1);
    g_csr_src[pos] = src[e];
}

// ---------------- node aggregation: half-warp per edge, 2-wide, single pass ----------------
__global__ void __launch_bounds__(256)
node_agg_kernel(float* __restrict__ out)
{
    int d = (blockIdx.x * blockDim.x + threadIdx.x) >> 5;
    int lane = threadIdx.x & 31;
    if (d >= NN) return;
    const int n = g_cnt[d];
    if (n == 0) return;   // out already holds the residual
    const int base = g_rowptr[d];

    const int half = lane >> 4;
    const int l16  = lane & 15;
    const int h    = l16 >> 2;         // features l16*8.. -> head l16/4
    const float adh = g_ad[(size_t)d * NH + h];

    float acc[8];
#pragma unroll
    for (int q = 0; q < 8; q++) acc[q] = 0.f;
    float den = 0.f;

    const int* cs = g_csr_src + base;
    const __half* xb = g_xh + (size_t)l16 * 8;

    int i = half;
    // 2-wide batch per half-warp (edges i, i+2)
    for (; i + 2 < n; i += 4) {
        int s0 = cs[i], s1 = cs[i + 2];
        float a0 = g_as[(size_t)s0 * NH + h];
        float a1 = g_as[(size_t)s1 * NH + h];
        uint4 v0 = *(const uint4*)(xb + (size_t)s0 * 128);
        uint4 v1 = *(const uint4*)(xb + (size_t)s1 * 128);
        float p0 = __expf(lrelu(a0 + adh));
        float p1 = __expf(lrelu(a1 + adh));
        den += p0 + p1;
        const __half2* b0 = (const __half2*)&v0;
        const __half2* b1 = (const __half2*)&v1;
#pragma unroll
        for (int q = 0; q < 4; q++) {
            float2 f0 = __half22float2(b0[q]);
            float2 f1 = __half22float2(b1[q]);
            acc[2 * q]     = fmaf(f0.x, p0, acc[2 * q]);
            acc[2 * q + 1] = fmaf(f0.y, p0, acc[2 * q + 1]);
            acc[2 * q]     = fmaf(f1.x, p1, acc[2 * q]);
            acc[2 * q + 1] = fmaf(f1.y, p1, acc[2 * q + 1]);
        }
    }
    if (i < n) {
        int s0 = cs[i];
        float a0 = g_as[(size_t)s0 * NH + h];
        uint4 v0 = *(const uint4*)(xb + (size_t)s0 * 128);
        float p0 = __expf(lrelu(a0 + adh));
        den += p0;
        const __half2* b0 = (const __half2*)&v0;
#pragma unroll
        for (int q = 0; q < 4; q++) {
            float2 f0 = __half22float2(b0[q]);
            acc[2 * q]     = fmaf(f0.x, p0, acc[2 * q]);
            acc[2 * q + 1] = fmaf(f0.y, p0, acc[2 * q + 1]);
        }
    }

    // combine the two halves
#pragma unroll
    for (int q = 0; q < 8; q++)
        acc[q] += __shfl_xor_sync(0xffffffffu, acc[q], 16);
    den += __shfl_xor_sync(0xffffffffu, den, 16);

    if (half == 0) {
        const float inv = 1.0f / den;
        float* o = out + (size_t)d * 128 + l16 * 8;
        float4 r0 = *(const float4*)o;
        float4 r1 = *(const float4*)(o + 4);
        r0.x = fmaf(acc[0], inv, r0.x);
        r0.y = fmaf(acc[1], inv, r0.y);
        r0.z = fmaf(acc[2], inv, r0.z);
        r0.w = fmaf(acc[3], inv, r0.w);
        r1.x = fmaf(acc[4], inv, r1.x);
        r1.y = fmaf(acc[5], inv, r1.y);
        r1.z = fmaf(acc[6], inv, r1.z);
        r1.w = fmaf(acc[7], inv, r1.w);
        *(float4*)o = r0;
        *(float4*)(o + 4) = r1;
    }
}

// ---------------- launch ----------------
extern "C" void kernel_launch(void* const* d_in, const int* in_sizes, int n_in,
                              void* d_out, int out_size)
{
    const float* feat    = (const float*)d_in[0];
    const float* W       = (const float*)d_in[1];
    const float* att_src = (const float*)d_in[2];
    const float* att_dst = (const float*)d_in[3];
    const float* Wres    = (const float*)d_in[4];
    const int*   src     = (const int*)d_in[5];
    const int*   dst     = (const int*)d_in[6];
    float* out = (float*)d_out;

    static cudaStream_t s2 = nullptr;
    static cudaEvent_t evFork = nullptr, evJoin = nullptr;
    if (!s2) {
        cudaFuncSetAttribute(gemm_tc,
                             cudaFuncAttributeMaxDynamicSharedMemorySize,
                             GEMM_SMEM);
        cudaStreamCreateWithFlags(&s2, cudaStreamNonBlocking);
        cudaEventCreateWithFlags(&evFork, cudaEventDisableTiming);
        cudaEventCreateWithFlags(&evJoin, cudaEventDisableTiming);
    }

    // fork: CSR build on s2, prep+GEMM on the main stream.
    // Enqueue order keeps gemm_tc 4th (profiler targeting).
    cudaEventRecord(evFork, 0);
    cudaStreamWaitEvent(s2, evFork, 0);

    zero_cnt_kernel<<<NB, 256, 0, s2>>>();                       // 1
    hist_kernel<<<(NE + 255) / 256, 256, 0, s2>>>(dst);          // 2
    prep_b<<<16, 256>>>(W, Wres);                                // 3
    gemm_tc<<<(NN + 127) / 128, 512, GEMM_SMEM>>>(feat, att_src, att_dst, out); // 4
    alloc_kernel<<<NB, 256, 0, s2>>>();                          // 5
    scatter_kernel<<<(NE + 255) / 256, 256, 0, s2>>>(src, dst);  // 6
    cudaEventRecord(evJoin, s2);

    // join: aggregation needs both GEMM outputs and the CSR
    cudaStreamWaitEvent(0, evJoin, 0);
    node_agg_kernel<<<(NN * 32 + 255) / 256, 256>>>(out);        // 7
}

// round 11
// speedup vs baseline: 1.1319x; 1.0752x over previous
#include <cuda_runtime.h>
#include <cuda_bf16.h>
#include <cuda_fp16.h>
#include <stdint.h>
#include <math.h>

// Problem constants (fixed by the dataset)
#define NN 100000      // nodes
#define NE 1600000     // edges
#define NH 4           // heads
#define NEG_SLOPE 0.2f
#define NB 391         // ceil(NN/256)

// ---------------- device scratch ----------------
__device__ __align__(16) __half g_xh[NN * 128];  // projected features, fp16
__device__ float g_as[NN * NH];         // per-node src logits (fp32)
__device__ float g_ad[NN * NH];         // per-node dst logits (fp32)
__device__ int   g_cnt[NN];
__device__ int   g_rowptr[NN];
__device__ int   g_cursor[NN];
__device__ int   g_total;
__device__ int   g_csr_src[NE];
// padded-transposed bf16 weights: [hi | lo], each [256 n][136 k]
__device__ __align__(16) __nv_bfloat16 g_Bpk[2 * 256 * 136];
// pre-split bf16 A (feat): [NN][128] each
__device__ __align__(16) __nv_bfloat16 g_Ahi[NN * 128];
__device__ __align__(16) __nv_bfloat16 g_Alo[NN * 128];

__device__ __forceinline__ float lrelu(float v) {
    return v > 0.0f ? v : NEG_SLOPE * v;
}

__device__ __forceinline__ uint32_t smem_u32(const void* p) {
    uint32_t a;
    asm("{ .reg .u64 t; cvta.to.shared.u64 t, %1; cvt.u32.u64 %0, t; }" : "=r"(a) : "l"(p));
    return a;
}

#define CP_ASYNC16(saddr, gptr)                                                \
    asm volatile("cp.async.cg.shared.global [%0], [%1], 16;"                   \
                 :: "r"(saddr), "l"(gptr))
#define CP_COMMIT() asm volatile("cp.async.commit_group;" ::: "memory")
#define CP_WAIT0()  asm volatile("cp.async.wait_group 0;" ::: "memory")
#define CP_WAIT1()  asm volatile("cp.async.wait_group 1;" ::: "memory")

#define LDSM4(r0, r1, r2, r3, addr)                                            \
    asm volatile("ldmatrix.sync.aligned.m8n8.x4.shared.b16 {%0,%1,%2,%3}, [%4];" \
                 : "=r"(r0), "=r"(r1), "=r"(r2), "=r"(r3) : "r"(addr))

#define MMA16816(c, a, b)                                                      \
    asm volatile(                                                              \
        "mma.sync.aligned.m16n8k16.row.col.f32.bf16.bf16.f32 "                 \
        "{%0,%1,%2,%3}, {%4,%5,%6,%7}, {%8,%9}, {%0,%1,%2,%3};"                \
        : "+f"((c)[0]), "+f"((c)[1]), "+f"((c)[2]), "+f"((c)[3])               \
        : "r"((a)[0]), "r"((a)[1]), "r"((a)[2]), "r"((a)[3]),                  \
          "r"((b)[0]), "r"((b)[1]))

// ---------------- prep: weights + feat -> split bf16 ----------------
// blocks 0..15: W/W_res -> transposed, split, padded (k-stride 136)
// blocks 16.. : feat -> g_Ahi/g_Alo (row-major, 128 elts/row)
__global__ void prep_ab(const float* __restrict__ W, const float* __restrict__ Wres,
                        const float* __restrict__ feat) {
    int b = blockIdx.x;
    int tid = threadIdx.x;
    if (b < 16) {
        int t = b * 256 + tid;          // < 4096
        int n  = t >> 4;
        int kg = (t & 15) * 8;
        const float* Wm = (n < 128) ? W : Wres;
        int col = n & 127;
        unsigned short hi[8], lo[8];
#pragma unroll
        for (int i = 0; i < 8; i++) {
            float a = Wm[(size_t)(kg + i) * 128 + col];
            __nv_bfloat16 h = __float2bfloat16(a);
            __nv_bfloat16 l = __float2bfloat16(a - __bfloat162float(h));
            hi[i] = *(unsigned short*)&h;
            lo[i] = *(unsigned short*)&l;
        }
        *(uint4*)(g_Bpk + (size_t)n * 136 + kg)             = *(uint4*)hi;
        *(uint4*)(g_Bpk + 256 * 136 + (size_t)n * 136 + kg) = *(uint4*)lo;
    } else {
        int i = (b - 16) * 256 + tid;
        if (i >= NN * 16) return;
        int row = i >> 4;
        int kg = (i & 15) * 8;
        float4 v0 = *(const float4*)(feat + (size_t)row * 128 + kg);
        float4 v1 = *(const float4*)(feat + (size_t)row * 128 + kg + 4);
        float a[8] = {v0.x, v0.y, v0.z, v0.w, v1.x, v1.y, v1.z, v1.w};
        unsigned short hi[8], lo[8];
#pragma unroll
        for (int q = 0; q < 8; q++) {
            __nv_bfloat16 h = __float2bfloat16(a[q]);
            __nv_bfloat16 l = __float2bfloat16(a[q] - __bfloat162float(h));
            hi[q] = *(unsigned short*)&h;
            lo[q] = *(unsigned short*)&l;
        }
        *(uint4*)(g_Ahi + (size_t)row * 128 + kg) = *(uint4*)hi;
        *(uint4*)(g_Alo + (size_t)row * 128 + kg) = *(uint4*)lo;
    }
}

// ---------------- tensor-core dual GEMM: K-chunked, double-buffered ----------------
// CTA: 256 threads (8 warps), tile M=64 x N=256, K in 4 chunks of 32 per pass,
// 3 passes (hi*hi, hi*lo, lo*hi) = 12 pipeline iterations.
// SMEM: Abuf[2][64 rows][80 B], Bbuf[2][256 n][80 B]  (pad 80 avoids bank conflicts)
#define SM_A 0u
#define SM_B 10240u
#define GEMM_SMEM 51200

__global__ void __launch_bounds__(256, 2)
gemm_tc(const float* __restrict__ att_src,
        const float* __restrict__ att_dst,
        float* __restrict__ out)
{
    extern __shared__ unsigned char smem[];
    const uint32_t sbase = smem_u32(smem);
    const int tid = threadIdx.x;
    const int row0 = blockIdx.x * 64;

    const int lane = tid & 31;
    const int wid = tid >> 5;
    const int wm = wid & 1;        // 2 m-tiles of 32 rows
    const int wn = wid >> 1;       // 4 n-tiles of 64 cols

    float c[2][8][4];
#pragma unroll
    for (int mi = 0; mi < 2; mi++)
#pragma unroll
        for (int ni = 0; ni < 8; ni++)
#pragma unroll
            for (int q = 0; q < 4; q++) c[mi][ni][q] = 0.f;

    // per-lane ldmatrix offsets (bytes) within a chunk buffer
    const uint32_t aRow = (uint32_t)(wm * 32 + (lane & 15));
    const uint32_t aKb  = (uint32_t)((lane >> 4) * 16);
    const uint32_t bN   = (uint32_t)(wn * 64 + ((lane >> 4) * 8) + (lane & 7));
    const uint32_t bKb  = (uint32_t)(((lane >> 3) & 1) * 16);

    // fetch iteration `it` into buffer `buf`
    auto fetch = [&](int it, int buf) {
        int p = it >> 2, ch = it & 3;
        const char* As = (const char*)((p == 2) ? g_Alo : g_Ahi);
        const char* Bs = (const char*)g_Bpk + ((p == 1) ? 69632 : 0);
        {   // A: 64 rows x 64 B -> 256 16B ops, 1/thread
            int r = tid >> 2, q = tid & 3;
            int gr = row0 + r;
            if (gr >= NN) gr = NN - 1;   // clamped rows discarded in epilogue
            CP_ASYNC16(sbase + SM_A + (uint32_t)(buf * 5120 + r * 80 + q * 16),
                       As + (size_t)gr * 256 + ch * 64 + q * 16);
        }
#pragma unroll
        for (int j = 0; j < 4; j++) {    // B: 256 n x 64 B -> 1024 ops, 4/thread
            int i = tid + j * 256;
            int n = i >> 2, q = i & 3;
            CP_ASYNC16(sbase + SM_B + (uint32_t)(buf * 20480 + n * 80 + q * 16),
                       Bs + n * 272 + ch * 64 + q * 16);
        }
    };

    fetch(0, 0);
    CP_COMMIT();

    for (int it = 0; it < 12; it++) {
        const int buf = it & 1;
        if (it < 11) {
            fetch(it + 1, buf ^ 1);
            CP_COMMIT();
            CP_WAIT1();
        } else {
            CP_WAIT0();
        }
        __syncthreads();

        const uint32_t aAddr0 = sbase + SM_A + (uint32_t)buf * 5120 + aRow * 80 + aKb;
        const uint32_t bAddr0 = sbase + SM_B + (uint32_t)buf * 20480 + bN * 80 + bKb;
#pragma unroll
        for (int ks = 0; ks < 2; ks++) {
            const uint32_t kb = (uint32_t)(ks * 32);
            uint32_t a[2][4];
            LDSM4(a[0][0], a[0][1], a[0][2], a[0][3], aAddr0 + kb);
            LDSM4(a[1][0], a[1][1], a[1][2], a[1][3], aAddr0 + 16 * 80 + kb);
            uint32_t b[8][2];
#pragma unroll
            for (int nj = 0; nj < 4; nj++) {
                LDSM4(b[2 * nj][0], b[2 * nj][1], b[2 * nj + 1][0], b[2 * nj + 1][1],
                      bAddr0 + (uint32_t)(nj * 16 * 80) + kb);
            }
#pragma unroll
            for (int mi = 0; mi < 2; mi++)
#pragma unroll
                for (int ni = 0; ni < 8; ni++)
                    MMA16816(c[mi][ni], a[mi], b[ni]);
        }
        __syncthreads();   // protect buf before it is refilled next iteration
    }

    // ---------------- epilogue ----------------
    const int qlane = lane >> 2;
    const int qcol  = (lane & 3) * 2;

#pragma unroll
    for (int mi = 0; mi < 2; mi++) {
        const int rA = row0 + wm * 32 + mi * 16 + qlane;
        const int rB = rA + 8;
#pragma unroll
        for (int ni = 0; ni < 8; ni++) {
            const int col = wn * 64 + ni * 8 + qcol;
            if (col < 128) {
                __half2 pA = __float22half2_rn(make_float2(c[mi][ni][0], c[mi][ni][1]));
                __half2 pB = __float22half2_rn(make_float2(c[mi][ni][2], c[mi][ni][3]));
                if (rA < NN) *(__half2*)(g_xh + (size_t)rA * 128 + col) = pA;
                if (rB < NN) *(__half2*)(g_xh + (size_t)rB * 128 + col) = pB;
            } else {
                if (rA < NN) *(float2*)(out + (size_t)rA * 128 + col - 128) =
                    make_float2(c[mi][ni][0], c[mi][ni][1]);
                if (rB < NN) *(float2*)(out + (size_t)rB * 128 + col - 128) =
                    make_float2(c[mi][ni][2], c[mi][ni][3]);
            }
        }
    }

    // fused attention logits for the x half (wn 0,1 hold cols 0..127), fp32-exact
    if (wn < 2) {
        const int hA = wn * 2;
        const int hB = wn * 2 + 1;
#pragma unroll
        for (int mi = 0; mi < 2; mi++) {
#pragma unroll
            for (int rp = 0; rp < 2; rp++) {
                float sa = 0.f, da = 0.f, sb = 0.f, db = 0.f;
#pragma unroll
                for (int ni = 0; ni < 4; ni++) {
                    const int col = wn * 64 + ni * 8 + qcol;
                    float x0 = c[mi][ni][2 * rp], x1 = c[mi][ni][2 * rp + 1];
                    sa = fmaf(x0, __ldg(att_src + col), sa);
                    sa = fmaf(x1, __ldg(att_src + col + 1), sa);
                    da = fmaf(x0, __ldg(att_dst + col), da);
                    da = fmaf(x1, __ldg(att_dst + col + 1), da);
                }
#pragma unroll
                for (int ni = 4; ni < 8; ni++) {
                    const int col = wn * 64 + ni * 8 + qcol;
                    float x0 = c[mi][ni][2 * rp], x1 = c[mi][ni][2 * rp + 1];
                    sb = fmaf(x0, __ldg(att_src + col), sb);
                    sb = fmaf(x1, __ldg(att_src + col + 1), sb);
                    db = fmaf(x0, __ldg(att_dst + col), db);
                    db = fmaf(x1, __ldg(att_dst + col + 1), db);
                }
                sa += __shfl_xor_sync(0xffffffffu, sa, 1);
                sa += __shfl_xor_sync(0xffffffffu, sa, 2);
                da += __shfl_xor_sync(0xffffffffu, da, 1);
                da += __shfl_xor_sync(0xffffffffu, da, 2);
                sb += __shfl_xor_sync(0xffffffffu, sb, 1);
                sb += __shfl_xor_sync(0xffffffffu, sb, 2);
                db += __shfl_xor_sync(0xffffffffu, db, 1);
                db += __shfl_xor_sync(0xffffffffu, db, 2);
                if ((lane & 3) == 0) {
                    const int r = row0 + wm * 32 + mi * 16 + rp * 8 + qlane;
                    if (r < NN) {
                        g_as[r * NH + hA] = sa;
                        g_ad[r * NH + hA] = da;
                        g_as[r * NH + hB] = sb;
                        g_ad[r * NH + hB] = db;
                    }
                }
            }
        }
    }
}

// ---------------- CSR build ----------------
__global__ void zero_cnt_kernel() {
    int i = blockIdx.x * blockDim.x + threadIdx.x;
    if (i < NN) g_cnt[i] = 0;
    if (i == 0) g_total = 0;
}

__global__ void hist_kernel(const int* __restrict__ dst) {
    int e = blockIdx.x * blockDim.x + threadIdx.x;
    if (e < NE) atomicAdd(&g_cnt[dst[e]], 1);
}

__global__ void alloc_kernel() {
    int i = blockIdx.x * blockDim.x + threadIdx.x;
    if (i >= NN) return;
    int c = g_cnt[i];
    int r = atomicAdd(&g_total, c);
    g_rowptr[i] = r;
    g_cursor[i] = r;
}

__global__ void scatter_kernel(const int* __restrict__ src,
                               const int* __restrict__ dst) {
    int e = blockIdx.x * blockDim.x + threadIdx.x;
    if (e >= NE) return;
    int d = dst[e];
    int pos = atomicAdd(&g_cursor[d], 1);
    g_csr_src[pos] = src[e];
}

// ---------------- node aggregation: half-warp per edge, 2-wide, single pass ----------------
__global__ void __launch_bounds__(256)
node_agg_kernel(float* __restrict__ out)
{
    int d = (blockIdx.x * blockDim.x + threadIdx.x) >> 5;
    int lane = threadIdx.x & 31;
    if (d >= NN) return;
    const int n = g_cnt[d];
    if (n == 0) return;   // out already holds the residual
    const int base = g_rowptr[d];

    const int half = lane >> 4;
    const int l16  = lane & 15;
    const int h    = l16 >> 2;         // features l16*8.. -> head l16/4
    const float adh = g_ad[(size_t)d * NH + h];

    float acc[8];
#pragma unroll
    for (int q = 0; q < 8; q++) acc[q] = 0.f;
    float den = 0.f;

    const int* cs = g_csr_src + base;
    const __half* xb = g_xh + (size_t)l16 * 8;

    int i = half;
    // 2-wide batch per half-warp (edges i, i+2)
    for (; i + 2 < n; i += 4) {
        int s0 = cs[i], s1 = cs[i + 2];
        float a0 = g_as[(size_t)s0 * NH + h];
        float a1 = g_as[(size_t)s1 * NH + h];
        uint4 v0 = *(const uint4*)(xb + (size_t)s0 * 128);
        uint4 v1 = *(const uint4*)(xb + (size_t)s1 * 128);
        float p0 = __expf(lrelu(a0 + adh));
        float p1 = __expf(lrelu(a1 + adh));
        den += p0 + p1;
        const __half2* b0 = (const __half2*)&v0;
        const __half2* b1 = (const __half2*)&v1;
#pragma unroll
        for (int q = 0; q < 4; q++) {
            float2 f0 = __half22float2(b0[q]);
            float2 f1 = __half22float2(b1[q]);
            acc[2 * q]     = fmaf(f0.x, p0, acc[2 * q]);
            acc[2 * q + 1] = fmaf(f0.y, p0, acc[2 * q + 1]);
            acc[2 * q]     = fmaf(f1.x, p1, acc[2 * q]);
            acc[2 * q + 1] = fmaf(f1.y, p1, acc[2 * q + 1]);
        }
    }
    if (i < n) {
        int s0 = cs[i];
        float a0 = g_as[(size_t)s0 * NH + h];
        uint4 v0 = *(const uint4*)(xb + (size_t)s0 * 128);
        float p0 = __expf(lrelu(a0 + adh));
        den += p0;
        const __half2* b0 = (const __half2*)&v0;
#pragma unroll
        for (int q = 0; q < 4; q++) {
            float2 f0 = __half22float2(b0[q]);
            acc[2 * q]     = fmaf(f0.x, p0, acc[2 * q]);
            acc[2 * q + 1] = fmaf(f0.y, p0, acc[2 * q + 1]);
        }
    }

    // combine the two halves
#pragma unroll
    for (int q = 0; q < 8; q++)
        acc[q] += __shfl_xor_sync(0xffffffffu, acc[q], 16);
    den += __shfl_xor_sync(0xffffffffu, den, 16);

    if (half == 0) {
        const float inv = 1.0f / den;
        float* o = out + (size_t)d * 128 + l16 * 8;
        float4 r0 = *(const float4*)o;
        float4 r1 = *(const float4*)(o + 4);
        r0.x = fmaf(acc[0], inv, r0.x);
        r0.y = fmaf(acc[1], inv, r0.y);
        r0.z = fmaf(acc[2], inv, r0.z);
        r0.w = fmaf(acc[3], inv, r0.w);
        r1.x = fmaf(acc[4], inv, r1.x);
        r1.y = fmaf(acc[5], inv, r1.y);
        r1.z = fmaf(acc[6], inv, r1.z);
        r1.w = fmaf(acc[7], inv, r1.w);
        *(float4*)o = r0;
        *(float4*)(o + 4) = r1;
    }
}

// ---------------- launch ----------------
extern "C" void kernel_launch(void* const* d_in, const int* in_sizes, int n_in,
                              void* d_out, int out_size)
{
    const float* feat    = (const float*)d_in[0];
    const float* W       = (const float*)d_in[1];
    const float* att_src = (const float*)d_in[2];
    const float* att_dst = (const float*)d_in[3];
    const float* Wres    = (const float*)d_in[4];
    const int*   src     = (const int*)d_in[5];
    const int*   dst     = (const int*)d_in[6];
    float* out = (float*)d_out;

    static cudaStream_t s2 = nullptr;
    static cudaEvent_t evFork = nullptr, evJoin = nullptr;
    if (!s2) {
        cudaFuncSetAttribute(gemm_tc,
                             cudaFuncAttributeMaxDynamicSharedMemorySize,
                             GEMM_SMEM);
        cudaStreamCreateWithFlags(&s2, cudaStreamNonBlocking);
        cudaEventCreateWithFlags(&evFork, cudaEventDisableTiming);
        cudaEventCreateWithFlags(&evJoin, cudaEventDisableTiming);
    }

    // fork: CSR build on s2, prep+GEMM on the main stream.
    // Enqueue order keeps gemm_tc 4th (profiler targeting).
    cudaEventRecord(evFork, 0);
    cudaStreamWaitEvent(s2, evFork, 0);

    zero_cnt_kernel<<<NB, 256, 0, s2>>>();                       // 1
    hist_kernel<<<(NE + 255) / 256, 256, 0, s2>>>(dst);          // 2
    prep_ab<<<16 + (NN * 16 + 255) / 256, 256>>>(W, Wres, feat); // 3
    gemm_tc<<<(NN + 63) / 64, 256, GEMM_SMEM>>>(att_src, att_dst, out); // 4
    alloc_kernel<<<NB, 256, 0, s2>>>();                          // 5
    scatter_kernel<<<(NE + 255) / 256, 256, 0, s2>>>(src, dst);  // 6
    cudaEventRecord(evJoin, s2);

    // join: aggregation needs both GEMM outputs and the CSR
    cudaStreamWaitEvent(0, evJoin, 0);
    node_agg_kernel<<<(NN * 32 + 255) / 256, 256>>>(out);        // 7
}

// round 12
// speedup vs baseline: 1.1981x; 1.0585x over previous
#include <cuda_runtime.h>
#include <cuda_bf16.h>
#include <cuda_fp16.h>
#include <stdint.h>
#include <math.h>

// Problem constants (fixed by the dataset)
#define NN 100000      // nodes
#define NE 1600000     // edges
#define NH 4           // heads
#define NEG_SLOPE 0.2f
#define NB 391         // ceil(NN/256)
#define NTILES 782     // ceil(NN/128)
#define NCTA 148       // persistent CTAs (1 per SM)

// ---------------- device scratch ----------------
__device__ __align__(16) __half g_xh[NN * 128];  // projected features, fp16
__device__ float g_as[NN * NH];         // per-node src logits (fp32)
__device__ float g_ad[NN * NH];         // per-node dst logits (fp32)
__device__ int   g_cnt[NN];
__device__ int   g_rowptr[NN];
__device__ int   g_cursor[NN];
__device__ int   g_total;
__device__ int   g_csr_src[NE];
// padded-transposed bf16 weights: [hi | lo], each [256 n][136 k] (stride 272 B)
__device__ __align__(16) __nv_bfloat16 g_Bpk[2 * 256 * 136];
// pre-split bf16 A (feat): [NN][128] each
__device__ __align__(16) __nv_bfloat16 g_Ahi[NN * 128];
__device__ __align__(16) __nv_bfloat16 g_Alo[NN * 128];

__device__ __forceinline__ float lrelu(float v) {
    return v > 0.0f ? v : NEG_SLOPE * v;
}

__device__ __forceinline__ uint32_t smem_u32(const void* p) {
    uint32_t a;
    asm("{ .reg .u64 t; cvta.to.shared.u64 t, %1; cvt.u32.u64 %0, t; }" : "=r"(a) : "l"(p));
    return a;
}

#define CP_ASYNC16(saddr, gptr)                                                \
    asm volatile("cp.async.cg.shared.global [%0], [%1], 16;"                   \
                 :: "r"(saddr), "l"(gptr))
#define CP_COMMIT() asm volatile("cp.async.commit_group;" ::: "memory")
#define CP_WAIT0()  asm volatile("cp.async.wait_group 0;" ::: "memory")
#define CP_WAIT1()  asm volatile("cp.async.wait_group 1;" ::: "memory")

#define LDSM4(r0, r1, r2, r3, addr)                                            \
    asm volatile("ldmatrix.sync.aligned.m8n8.x4.shared.b16 {%0,%1,%2,%3}, [%4];" \
                 : "=r"(r0), "=r"(r1), "=r"(r2), "=r"(r3) : "r"(addr))

#define MMA16816(c, a, b)                                                      \
    asm volatile(                                                              \
        "mma.sync.aligned.m16n8k16.row.col.f32.bf16.bf16.f32 "                 \
        "{%0,%1,%2,%3}, {%4,%5,%6,%7}, {%8,%9}, {%0,%1,%2,%3};"                \
        : "+f"((c)[0]), "+f"((c)[1]), "+f"((c)[2]), "+f"((c)[3])               \
        : "r"((a)[0]), "r"((a)[1]), "r"((a)[2]), "r"((a)[3]),                  \
          "r"((b)[0]), "r"((b)[1]))

// ---------------- prep: weights + feat -> split bf16 ----------------
__global__ void prep_ab(const float* __restrict__ W, const float* __restrict__ Wres,
                        const float* __restrict__ feat) {
    int b = blockIdx.x;
    int tid = threadIdx.x;
    if (b < 16) {
        int t = b * 256 + tid;          // < 4096
        int n  = t >> 4;
        int kg = (t & 15) * 8;
        const float* Wm = (n < 128) ? W : Wres;
        int col = n & 127;
        unsigned short hi[8], lo[8];
#pragma unroll
        for (int i = 0; i < 8; i++) {
            float a = Wm[(size_t)(kg + i) * 128 + col];
            __nv_bfloat16 h = __float2bfloat16(a);
            __nv_bfloat16 l = __float2bfloat16(a - __bfloat162float(h));
            hi[i] = *(unsigned short*)&h;
            lo[i] = *(unsigned short*)&l;
        }
        *(uint4*)(g_Bpk + (size_t)n * 136 + kg)             = *(uint4*)hi;
        *(uint4*)(g_Bpk + 256 * 136 + (size_t)n * 136 + kg) = *(uint4*)lo;
    } else {
        int i = (b - 16) * 256 + tid;
        if (i >= NN * 16) return;
        int row = i >> 4;
        int kg = (i & 15) * 8;
        float4 v0 = *(const float4*)(feat + (size_t)row * 128 + kg);
        float4 v1 = *(const float4*)(feat + (size_t)row * 128 + kg + 4);
        float a[8] = {v0.x, v0.y, v0.z, v0.w, v1.x, v1.y, v1.z, v1.w};
        unsigned short hi[8], lo[8];
#pragma unroll
        for (int q = 0; q < 8; q++) {
            __nv_bfloat16 h = __float2bfloat16(a[q]);
            __nv_bfloat16 l = __float2bfloat16(a[q] - __bfloat162float(h));
            hi[q] = *(unsigned short*)&h;
            lo[q] = *(unsigned short*)&l;
        }
        *(uint4*)(g_Ahi + (size_t)row * 128 + kg) = *(uint4*)hi;
        *(uint4*)(g_Alo + (size_t)row * 128 + kg) = *(uint4*)lo;
    }
}

// ---------------- persistent tensor-core dual GEMM ----------------
// 148 CTAs x 512 threads. B (hi|lo, 139264 B) resident in SMEM, loaded once.
// Each CTA loops over row-tiles of 128; per tile 12 iterations (3 passes x 4
// k-chunks of 32), streaming A chunks (128 rows x 64 B, padded stride 80)
// through 3 SMEM slots with cp.async, one __syncthreads per iteration.
#define SM_B    0u
#define SM_A    139264u
#define A_SLOT  10240u
#define GEMM_SMEM 169984

__device__ __forceinline__ void fetch_a(uint32_t sbase, int row0, int it,
                                        int slot, int tid) {
    int p = it >> 2, ch = it & 3;
    const char* As = (const char*)((p == 2) ? g_Alo : g_Ahi);
    int r = tid >> 2, q = tid & 3;
    int gr = row0 + r;
    if (gr >= NN) gr = NN - 1;   // clamped rows discarded in epilogue
    CP_ASYNC16(sbase + SM_A + (uint32_t)(slot * (int)A_SLOT + r * 80 + q * 16),
               As + (size_t)gr * 256 + ch * 64 + q * 16);
}

__global__ void __launch_bounds__(512, 1)
gemm_tc(const float* __restrict__ att_src,
        const float* __restrict__ att_dst,
        float* __restrict__ out)
{
    extern __shared__ unsigned char smem[];
    const uint32_t sbase = smem_u32(smem);
    const int tid = threadIdx.x;

    // ---- load resident B once: 139264 B = 8704 x 16B, 17 per thread ----
    {
        const char* bs = (const char*)g_Bpk;
#pragma unroll
        for (int j = 0; j < 17; j++) {
            uint32_t off = (uint32_t)(tid + j * 512) * 16;
            CP_ASYNC16(sbase + SM_B + off, bs + off);
        }
        CP_COMMIT();
    }

    const int lane = tid & 31;
    const int wid = tid >> 5;
    const int wm = wid & 3;        // 4 m-tiles of 32 rows
    const int wn = wid >> 2;       // 4 n-tiles of 64 cols

    const uint32_t aRow = (uint32_t)(wm * 32 + (lane & 15));
    const uint32_t aKb  = (uint32_t)((lane >> 4) * 16);
    const uint32_t bN   = (uint32_t)(wn * 64 + ((lane >> 4) * 8) + (lane & 7));
    const uint32_t bKb  = (uint32_t)(((lane >> 3) & 1) * 16);
    const int qlane = lane >> 2;
    const int qcol  = (lane & 3) * 2;

    // prologue for the first tile
    int tile = blockIdx.x;
    if (tile < NTILES) {
        fetch_a(sbase, tile * 128, 0, 0, tid);
        CP_COMMIT();
        fetch_a(sbase, tile * 128, 1, 1, tid);
        CP_COMMIT();
    }

    for (; tile < NTILES; tile += NCTA) {
        const int row0 = tile * 128;

        float c[2][8][4];
#pragma unroll
        for (int mi = 0; mi < 2; mi++)
#pragma unroll
            for (int ni = 0; ni < 8; ni++)
#pragma unroll
                for (int q = 0; q < 4; q++) c[mi][ni][q] = 0.f;

        // ---- mainloop: 12 iterations, 3-stage pipeline ----
        for (int it = 0; it < 12; it++) {
            if (it < 11) CP_WAIT1(); else CP_WAIT0();
            __syncthreads();
            if (it < 10) {
                fetch_a(sbase, row0, it + 2, (it + 2) % 3, tid);
                CP_COMMIT();
            }
            const int p = it >> 2, ch = it & 3;
            const int slot = it % 3;
            const uint32_t aAddr0 = sbase + SM_A + (uint32_t)slot * A_SLOT +
                                    aRow * 80 + aKb;
            const uint32_t bAddr0 = sbase + SM_B + (p == 1 ? 69632u : 0u) +
                                    bN * 272 + bKb + (uint32_t)(ch * 64);
#pragma unroll
            for (int ks = 0; ks < 2; ks++) {
                const uint32_t kb = (uint32_t)(ks * 32);
                uint32_t a[2][4];
                LDSM4(a[0][0], a[0][1], a[0][2], a[0][3], aAddr0 + kb);
                LDSM4(a[1][0], a[1][1], a[1][2], a[1][3], aAddr0 + 16 * 80 + kb);
                uint32_t b[8][2];
#pragma unroll
                for (int nj = 0; nj < 4; nj++) {
                    LDSM4(b[2 * nj][0], b[2 * nj][1], b[2 * nj + 1][0], b[2 * nj + 1][1],
                          bAddr0 + (uint32_t)(nj * 16 * 272) + kb);
                }
#pragma unroll
                for (int mi = 0; mi < 2; mi++)
#pragma unroll
                    for (int ni = 0; ni < 8; ni++)
                        MMA16816(c[mi][ni], a[mi], b[ni]);
            }
        }

        // prefetch the next tile's first two chunks under the epilogue
        if (tile + NCTA < NTILES) {
            fetch_a(sbase, (tile + NCTA) * 128, 0, 0, tid);
            CP_COMMIT();
            fetch_a(sbase, (tile + NCTA) * 128, 1, 1, tid);
            CP_COMMIT();
        }

        // ---- epilogue ----
#pragma unroll
        for (int mi = 0; mi < 2; mi++) {
            const int rA = row0 + wm * 32 + mi * 16 + qlane;
            const int rB = rA + 8;
#pragma unroll
            for (int ni = 0; ni < 8; ni++) {
                const int col = wn * 64 + ni * 8 + qcol;
                if (col < 128) {
                    __half2 pA = __float22half2_rn(make_float2(c[mi][ni][0], c[mi][ni][1]));
                    __half2 pB = __float22half2_rn(make_float2(c[mi][ni][2], c[mi][ni][3]));
                    if (rA < NN) *(__half2*)(g_xh + (size_t)rA * 128 + col) = pA;
                    if (rB < NN) *(__half2*)(g_xh + (size_t)rB * 128 + col) = pB;
                } else {
                    if (rA < NN) *(float2*)(out + (size_t)rA * 128 + col - 128) =
                        make_float2(c[mi][ni][0], c[mi][ni][1]);
                    if (rB < NN) *(float2*)(out + (size_t)rB * 128 + col - 128) =
                        make_float2(c[mi][ni][2], c[mi][ni][3]);
                }
            }
        }

        // fused attention logits for the x half (wn 0,1), fp32-exact
        if (wn < 2) {
            const int hA = wn * 2;
            const int hB = wn * 2 + 1;
#pragma unroll
            for (int mi = 0; mi < 2; mi++) {
#pragma unroll
                for (int rp = 0; rp < 2; rp++) {
                    float sa = 0.f, da = 0.f, sb = 0.f, db = 0.f;
#pragma unroll
                    for (int ni = 0; ni < 4; ni++) {
                        const int col = wn * 64 + ni * 8 + qcol;
                        float x0 = c[mi][ni][2 * rp], x1 = c[mi][ni][2 * rp + 1];
                        sa = fmaf(x0, __ldg(att_src + col), sa);
                        sa = fmaf(x1, __ldg(att_src + col + 1), sa);
                        da = fmaf(x0, __ldg(att_dst + col), da);
                        da = fmaf(x1, __ldg(att_dst + col + 1), da);
                    }
#pragma unroll
                    for (int ni = 4; ni < 8; ni++) {
                        const int col = wn * 64 + ni * 8 + qcol;
                        float x0 = c[mi][ni][2 * rp], x1 = c[mi][ni][2 * rp + 1];
                        sb = fmaf(x0, __ldg(att_src + col), sb);
                        sb = fmaf(x1, __ldg(att_src + col + 1), sb);
                        db = fmaf(x0, __ldg(att_dst + col), db);
                        db = fmaf(x1, __ldg(att_dst + col + 1), db);
                    }
                    sa += __shfl_xor_sync(0xffffffffu, sa, 1);
                    sa += __shfl_xor_sync(0xffffffffu, sa, 2);
                    da += __shfl_xor_sync(0xffffffffu, da, 1);
                    da += __shfl_xor_sync(0xffffffffu, da, 2);
                    sb += __shfl_xor_sync(0xffffffffu, sb, 1);
                    sb += __shfl_xor_sync(0xffffffffu, sb, 2);
                    db += __shfl_xor_sync(0xffffffffu, db, 1);
                    db += __shfl_xor_sync(0xffffffffu, db, 2);
                    if ((lane & 3) == 0) {
                        const int r = row0 + wm * 32 + mi * 16 + rp * 8 + qlane;
                        if (r < NN) {
                            g_as[r * NH + hA] = sa;
                            g_ad[r * NH + hA] = da;
                            g_as[r * NH + hB] = sb;
                            g_ad[r * NH + hB] = db;
                        }
                    }
                }
            }
        }
    }
}

// ---------------- CSR build ----------------
__global__ void zero_cnt_kernel() {
    int i = blockIdx.x * blockDim.x + threadIdx.x;
    if (i < NN) g_cnt[i] = 0;
    if (i == 0) g_total = 0;
}

__global__ void hist_kernel(const int* __restrict__ dst) {
    int e = blockIdx.x * blockDim.x + threadIdx.x;
    if (e < NE) atomicAdd(&g_cnt[dst[e]], 1);
}

__global__ void alloc_kernel() {
    int i = blockIdx.x * blockDim.x + threadIdx.x;
    if (i >= NN) return;
    int c = g_cnt[i];
    int r = atomicAdd(&g_total, c);
    g_rowptr[i] = r;
    g_cursor[i] = r;
}

__global__ void scatter_kernel(const int* __restrict__ src,
                               const int* __restrict__ dst) {
    int e = blockIdx.x * blockDim.x + threadIdx.x;
    if (e >= NE) return;
    int d = dst[e];
    int pos = atomicAdd(&g_cursor[d], 1);
    g_csr_src[pos] = src[e];
}

// ---------------- node aggregation: half-warp per edge, 2-wide, single pass ----------------
__global__ void __launch_bounds__(256)
node_agg_kernel(float* __restrict__ out)
{
    int d = (blockIdx.x * blockDim.x + threadIdx.x) >> 5;
    int lane = threadIdx.x & 31;
    if (d >= NN) return;
    const int n = g_cnt[d];
    if (n == 0) return;   // out already holds the residual
    const int base = g_rowptr[d];

    const int half = lane >> 4;
    const int l16  = lane & 15;
    const int h    = l16 >> 2;
    const float adh = g_ad[(size_t)d * NH + h];

    float acc[8];
#pragma unroll
    for (int q = 0; q < 8; q++) acc[q] = 0.f;
    float den = 0.f;

    const int* cs = g_csr_src + base;
    const __half* xb = g_xh + (size_t)l16 * 8;

    int i = half;
    for (; i + 2 < n; i += 4) {
        int s0 = cs[i], s1 = cs[i + 2];
        float a0 = g_as[(size_t)s0 * NH + h];
        float a1 = g_as[(size_t)s1 * NH + h];
        uint4 v0 = *(const uint4*)(xb + (size_t)s0 * 128);
        uint4 v1 = *(const uint4*)(xb + (size_t)s1 * 128);
        float p0 = __expf(lrelu(a0 + adh));
        float p1 = __expf(lrelu(a1 + adh));
        den += p0 + p1;
        const __half2* b0 = (const __half2*)&v0;
        const __half2* b1 = (const __half2*)&v1;
#pragma unroll
        for (int q = 0; q < 4; q++) {
            float2 f0 = __half22float2(b0[q]);
            float2 f1 = __half22float2(b1[q]);
            acc[2 * q]     = fmaf(f0.x, p0, acc[2 * q]);
            acc[2 * q + 1] = fmaf(f0.y, p0, acc[2 * q + 1]);
            acc[2 * q]     = fmaf(f1.x, p1, acc[2 * q]);
            acc[2 * q + 1] = fmaf(f1.y, p1, acc[2 * q + 1]);
        }
    }
    if (i < n) {
        int s0 = cs[i];
        float a0 = g_as[(size_t)s0 * NH + h];
        uint4 v0 = *(const uint4*)(xb + (size_t)s0 * 128);
        float p0 = __expf(lrelu(a0 + adh));
        den += p0;
        const __half2* b0 = (const __half2*)&v0;
#pragma unroll
        for (int q = 0; q < 4; q++) {
            float2 f0 = __half22float2(b0[q]);
            acc[2 * q]     = fmaf(f0.x, p0, acc[2 * q]);
            acc[2 * q + 1] = fmaf(f0.y, p0, acc[2 * q + 1]);
        }
    }

#pragma unroll
    for (int q = 0; q < 8; q++)
        acc[q] += __shfl_xor_sync(0xffffffffu, acc[q], 16);
    den += __shfl_xor_sync(0xffffffffu, den, 16);

    if (half == 0) {
        const float inv = 1.0f / den;
        float* o = out + (size_t)d * 128 + l16 * 8;
        float4 r0 = *(const float4*)o;
        float4 r1 = *(const float4*)(o + 4);
        r0.x = fmaf(acc[0], inv, r0.x);
        r0.y = fmaf(acc[1], inv, r0.y);
        r0.z = fmaf(acc[2], inv, r0.z);
        r0.w = fmaf(acc[3], inv, r0.w);
        r1.x = fmaf(acc[4], inv, r1.x);
        r1.y = fmaf(acc[5], inv, r1.y);
        r1.z = fmaf(acc[6], inv, r1.z);
        r1.w = fmaf(acc[7], inv, r1.w);
        *(float4*)o = r0;
        *(float4*)(o + 4) = r1;
    }
}

// ---------------- launch ----------------
extern "C" void kernel_launch(void* const* d_in, const int* in_sizes, int n_in,
                              void* d_out, int out_size)
{
    const float* feat    = (const float*)d_in[0];
    const float* W       = (const float*)d_in[1];
    const float* att_src = (const float*)d_in[2];
    const float* att_dst = (const float*)d_in[3];
    const float* Wres    = (const float*)d_in[4];
    const int*   src     = (const int*)d_in[5];
    const int*   dst     = (const int*)d_in[6];
    float* out = (float*)d_out;

    static cudaStream_t s2 = nullptr;
    static cudaEvent_t evFork = nullptr, evJoin = nullptr;
    if (!s2) {
        cudaFuncSetAttribute(gemm_tc,
                             cudaFuncAttributeMaxDynamicSharedMemorySize,
                             GEMM_SMEM);
        cudaStreamCreateWithFlags(&s2, cudaStreamNonBlocking);
        cudaEventCreateWithFlags(&evFork, cudaEventDisableTiming);
        cudaEventCreateWithFlags(&evJoin, cudaEventDisableTiming);
    }

    // fork: CSR build on s2, prep+GEMM on the main stream.
    // Enqueue order keeps gemm_tc 4th (profiler targeting).
    cudaEventRecord(evFork, 0);
    cudaStreamWaitEvent(s2, evFork, 0);

    zero_cnt_kernel<<<NB, 256, 0, s2>>>();                       // 1
    hist_kernel<<<(NE + 255) / 256, 256, 0, s2>>>(dst);          // 2
    prep_ab<<<16 + (NN * 16 + 255) / 256, 256>>>(W, Wres, feat); // 3
    gemm_tc<<<NCTA, 512, GEMM_SMEM>>>(att_src, att_dst, out);    // 4
    alloc_kernel<<<NB, 256, 0, s2>>>();                          // 5
    scatter_kernel<<<(NE + 255) / 256, 256, 0, s2>>>(src, dst);  // 6
    cudaEventRecord(evJoin, s2);

    // join: aggregation needs both GEMM outputs and the CSR
    cudaStreamWaitEvent(0, evJoin, 0);
    node_agg_kernel<<<(NN * 32 + 255) / 256, 256>>>(out);        // 7
}

// round 13
// speedup vs baseline: 1.3020x; 1.0867x over previous
#include <cuda_runtime.h>
#include <cuda_bf16.h>
#include <cuda_fp16.h>
#include <stdint.h>
#include <math.h>

// Problem constants (fixed by the dataset)
#define NN 100000      // nodes
#define NE 1600000     // edges
#define NH 4           // heads
#define NEG_SLOPE 0.2f
#define NB 391         // ceil(NN/256)
#define NTILES 782     // ceil(NN/128)
#define NCTA 148       // persistent CTAs (1 per SM)

// ---------------- device scratch ----------------
__device__ __align__(16) __half g_xh[NN * 128];  // projected features, fp16
__device__ float g_as[NN * NH];         // per-node src logits (fp32)
__device__ float g_ad[NN * NH];         // per-node dst logits (fp32)
__device__ int   g_cnt[NN];
__device__ int   g_rowptr[NN];
__device__ int   g_cursor[NN];
__device__ int   g_total;
__device__ int   g_csr_src[NE];
// padded-transposed bf16 weights: [hi | lo], each [256 n][136 k] (stride 272 B)
__device__ __align__(16) __nv_bfloat16 g_Bpk[2 * 256 * 136];
// pre-split bf16 A (feat): [NN][128] each
__device__ __align__(16) __nv_bfloat16 g_Ahi[NN * 128];
__device__ __align__(16) __nv_bfloat16 g_Alo[NN * 128];

__device__ __forceinline__ float lrelu(float v) {
    return v > 0.0f ? v : NEG_SLOPE * v;
}

__device__ __forceinline__ uint32_t smem_u32(const void* p) {
    uint32_t a;
    asm("{ .reg .u64 t; cvta.to.shared.u64 t, %1; cvt.u32.u64 %0, t; }" : "=r"(a) : "l"(p));
    return a;
}

#define CP_ASYNC16(saddr, gptr)                                                \
    asm volatile("cp.async.cg.shared.global [%0], [%1], 16;"                   \
                 :: "r"(saddr), "l"(gptr))
#define CP_COMMIT() asm volatile("cp.async.commit_group;" ::: "memory")
#define CP_WAIT0()  asm volatile("cp.async.wait_group 0;" ::: "memory")
#define CP_WAIT1()  asm volatile("cp.async.wait_group 1;" ::: "memory")

#define LDSM4(r0, r1, r2, r3, addr)                                            \
    asm volatile("ldmatrix.sync.aligned.m8n8.x4.shared.b16 {%0,%1,%2,%3}, [%4];" \
                 : "=r"(r0), "=r"(r1), "=r"(r2), "=r"(r3) : "r"(addr))

#define MMA16816(c, a, b)                                                      \
    asm volatile(                                                              \
        "mma.sync.aligned.m16n8k16.row.col.f32.bf16.bf16.f32 "                 \
        "{%0,%1,%2,%3}, {%4,%5,%6,%7}, {%8,%9}, {%0,%1,%2,%3};"                \
        : "+f"((c)[0]), "+f"((c)[1]), "+f"((c)[2]), "+f"((c)[3])               \
        : "r"((a)[0]), "r"((a)[1]), "r"((a)[2]), "r"((a)[3]),                  \
          "r"((b)[0]), "r"((b)[1]))

// ---------------- prep: weights + feat -> split bf16 ----------------
__global__ void prep_ab(const float* __restrict__ W, const float* __restrict__ Wres,
                        const float* __restrict__ feat) {
    int b = blockIdx.x;
    int tid = threadIdx.x;
    if (b < 16) {
        int t = b * 256 + tid;          // < 4096
        int n  = t >> 4;
        int kg = (t & 15) * 8;
        const float* Wm = (n < 128) ? W : Wres;
        int col = n & 127;
        unsigned short hi[8], lo[8];
#pragma unroll
        for (int i = 0; i < 8; i++) {
            float a = Wm[(size_t)(kg + i) * 128 + col];
            __nv_bfloat16 h = __float2bfloat16(a);
            __nv_bfloat16 l = __float2bfloat16(a - __bfloat162float(h));
            hi[i] = *(unsigned short*)&h;
            lo[i] = *(unsigned short*)&l;
        }
        *(uint4*)(g_Bpk + (size_t)n * 136 + kg)             = *(uint4*)hi;
        *(uint4*)(g_Bpk + 256 * 136 + (size_t)n * 136 + kg) = *(uint4*)lo;
    } else {
        int i = (b - 16) * 256 + tid;
        if (i >= NN * 16) return;
        int row = i >> 4;
        int kg = (i & 15) * 8;
        float4 v0 = *(const float4*)(feat + (size_t)row * 128 + kg);
        float4 v1 = *(const float4*)(feat + (size_t)row * 128 + kg + 4);
        float a[8] = {v0.x, v0.y, v0.z, v0.w, v1.x, v1.y, v1.z, v1.w};
        unsigned short hi[8], lo[8];
#pragma unroll
        for (int q = 0; q < 8; q++) {
            __nv_bfloat16 h = __float2bfloat16(a[q]);
            __nv_bfloat16 l = __float2bfloat16(a[q] - __bfloat162float(h));
            hi[q] = *(unsigned short*)&h;
            lo[q] = *(unsigned short*)&l;
        }
        *(uint4*)(g_Ahi + (size_t)row * 128 + kg) = *(uint4*)hi;
        *(uint4*)(g_Alo + (size_t)row * 128 + kg) = *(uint4*)lo;
    }
}

// ---------------- persistent tensor-core dual GEMM ----------------
// 148 CTAs x 512 threads. B (hi|lo, 139264 B) resident in SMEM, loaded once.
// Per tile: 6 iterations (3 passes x 2 k-chunks of 64), A chunks 128 rows x
// 128 B (padded stride 144) through 3 SMEM slots, 1 __syncthreads/iteration.
#define SM_B    0u
#define SM_A    139264u
#define A_SLOT  18432u
#define GEMM_SMEM 194560

__device__ __forceinline__ void fetch_a(uint32_t sbase, int row0, int it,
                                        int slot, int tid) {
    int p = it >> 1, ch = it & 1;
    const char* As = (const char*)((p == 2) ? g_Alo : g_Ahi);
#pragma unroll
    for (int j = 0; j < 2; j++) {
        int i = tid + j * 512;          // 1024 16B chunks
        int r = i >> 3;                 // 8 chunks per 128B row
        int q = i & 7;
        int gr = row0 + r;
        if (gr >= NN) gr = NN - 1;      // clamped rows discarded in epilogue
        CP_ASYNC16(sbase + SM_A + (uint32_t)(slot * (int)A_SLOT + r * 144 + q * 16),
                   As + (size_t)gr * 256 + ch * 128 + q * 16);
    }
}

__global__ void __launch_bounds__(512, 1)
gemm_tc(const float* __restrict__ att_src,
        const float* __restrict__ att_dst,
        float* __restrict__ out)
{
    extern __shared__ unsigned char smem[];
    const uint32_t sbase = smem_u32(smem);
    const int tid = threadIdx.x;

    // ---- load resident B once: 139264 B = 8704 x 16B, 17 per thread ----
    {
        const char* bs = (const char*)g_Bpk;
#pragma unroll
        for (int j = 0; j < 17; j++) {
            uint32_t off = (uint32_t)(tid + j * 512) * 16;
            CP_ASYNC16(sbase + SM_B + off, bs + off);
        }
        CP_COMMIT();
    }

    const int lane = tid & 31;
    const int wid = tid >> 5;
    const int wm = wid & 3;        // 4 m-tiles of 32 rows
    const int wn = wid >> 2;       // 4 n-tiles of 64 cols

    const uint32_t aRow = (uint32_t)(wm * 32 + (lane & 15));
    const uint32_t aKb  = (uint32_t)((lane >> 4) * 16);
    const uint32_t bN   = (uint32_t)(wn * 64 + ((lane >> 4) * 8) + (lane & 7));
    const uint32_t bKb  = (uint32_t)(((lane >> 3) & 1) * 16);
    const int qlane = lane >> 2;
    const int qcol  = (lane & 3) * 2;

    // prologue for the first tile
    int tile = blockIdx.x;
    if (tile < NTILES) {
        fetch_a(sbase, tile * 128, 0, 0, tid);
        CP_COMMIT();
        fetch_a(sbase, tile * 128, 1, 1, tid);
        CP_COMMIT();
    }

    for (; tile < NTILES; tile += NCTA) {
        const int row0 = tile * 128;

        float c[2][8][4];
#pragma unroll
        for (int mi = 0; mi < 2; mi++)
#pragma unroll
            for (int ni = 0; ni < 8; ni++)
#pragma unroll
                for (int q = 0; q < 4; q++) c[mi][ni][q] = 0.f;

        // ---- mainloop: 6 iterations, 3-stage pipeline ----
        for (int it = 0; it < 6; it++) {
            if (it < 5) CP_WAIT1(); else CP_WAIT0();
            __syncthreads();
            if (it < 4) {
                fetch_a(sbase, row0, it + 2, (it + 2) % 3, tid);
                CP_COMMIT();
            }
            const int p = it >> 1, ch = it & 1;
            const int slot = it % 3;
            const uint32_t aAddr0 = sbase + SM_A + (uint32_t)slot * A_SLOT +
                                    aRow * 144 + aKb;
            const uint32_t bAddr0 = sbase + SM_B + (p == 1 ? 69632u : 0u) +
                                    bN * 272 + bKb + (uint32_t)(ch * 128);
#pragma unroll
            for (int ks = 0; ks < 4; ks++) {
                const uint32_t kb = (uint32_t)(ks * 32);
                uint32_t a[2][4];
                LDSM4(a[0][0], a[0][1], a[0][2], a[0][3], aAddr0 + kb);
                LDSM4(a[1][0], a[1][1], a[1][2], a[1][3], aAddr0 + 16 * 144 + kb);
                uint32_t b[8][2];
#pragma unroll
                for (int nj = 0; nj < 4; nj++) {
                    LDSM4(b[2 * nj][0], b[2 * nj][1], b[2 * nj + 1][0], b[2 * nj + 1][1],
                          bAddr0 + (uint32_t)(nj * 16 * 272) + kb);
                }
#pragma unroll
                for (int mi = 0; mi < 2; mi++)
#pragma unroll
                    for (int ni = 0; ni < 8; ni++)
                        MMA16816(c[mi][ni], a[mi], b[ni]);
            }
        }

        // prefetch the next tile's first two chunks under the epilogue
        if (tile + NCTA < NTILES) {
            fetch_a(sbase, (tile + NCTA) * 128, 0, 0, tid);
            CP_COMMIT();
            fetch_a(sbase, (tile + NCTA) * 128, 1, 1, tid);
            CP_COMMIT();
        }

        // ---- epilogue ----
#pragma unroll
        for (int mi = 0; mi < 2; mi++) {
            const int rA = row0 + wm * 32 + mi * 16 + qlane;
            const int rB = rA + 8;
#pragma unroll
            for (int ni = 0; ni < 8; ni++) {
                const int col = wn * 64 + ni * 8 + qcol;
                if (col < 128) {
                    __half2 pA = __float22half2_rn(make_float2(c[mi][ni][0], c[mi][ni][1]));
                    __half2 pB = __float22half2_rn(make_float2(c[mi][ni][2], c[mi][ni][3]));
                    if (rA < NN) *(__half2*)(g_xh + (size_t)rA * 128 + col) = pA;
                    if (rB < NN) *(__half2*)(g_xh + (size_t)rB * 128 + col) = pB;
                } else {
                    if (rA < NN) *(float2*)(out + (size_t)rA * 128 + col - 128) =
                        make_float2(c[mi][ni][0], c[mi][ni][1]);
                    if (rB < NN) *(float2*)(out + (size_t)rB * 128 + col - 128) =
                        make_float2(c[mi][ni][2], c[mi][ni][3]);
                }
            }
        }

        // fused attention logits for the x half (wn 0,1), fp32-exact
        if (wn < 2) {
            const int hA = wn * 2;
            const int hB = wn * 2 + 1;
#pragma unroll
            for (int mi = 0; mi < 2; mi++) {
#pragma unroll
                for (int rp = 0; rp < 2; rp++) {
                    float sa = 0.f, da = 0.f, sb = 0.f, db = 0.f;
#pragma unroll
                    for (int ni = 0; ni < 4; ni++) {
                        const int col = wn * 64 + ni * 8 + qcol;
                        float x0 = c[mi][ni][2 * rp], x1 = c[mi][ni][2 * rp + 1];
                        sa = fmaf(x0, __ldg(att_src + col), sa);
                        sa = fmaf(x1, __ldg(att_src + col + 1), sa);
                        da = fmaf(x0, __ldg(att_dst + col), da);
                        da = fmaf(x1, __ldg(att_dst + col + 1), da);
                    }
#pragma unroll
                    for (int ni = 4; ni < 8; ni++) {
                        const int col = wn * 64 + ni * 8 + qcol;
                        float x0 = c[mi][ni][2 * rp], x1 = c[mi][ni][2 * rp + 1];
                        sb = fmaf(x0, __ldg(att_src + col), sb);
                        sb = fmaf(x1, __ldg(att_src + col + 1), sb);
                        db = fmaf(x0, __ldg(att_dst + col), db);
                        db = fmaf(x1, __ldg(att_dst + col + 1), db);
                    }
                    sa += __shfl_xor_sync(0xffffffffu, sa, 1);
                    sa += __shfl_xor_sync(0xffffffffu, sa, 2);
                    da += __shfl_xor_sync(0xffffffffu, da, 1);
                    da += __shfl_xor_sync(0xffffffffu, da, 2);
                    sb += __shfl_xor_sync(0xffffffffu, sb, 1);
                    sb += __shfl_xor_sync(0xffffffffu, sb, 2);
                    db += __shfl_xor_sync(0xffffffffu, db, 1);
                    db += __shfl_xor_sync(0xffffffffu, db, 2);
                    if ((lane & 3) == 0) {
                        const int r = row0 + wm * 32 + mi * 16 + rp * 8 + qlane;
                        if (r < NN) {
                            g_as[r * NH + hA] = sa;
                            g_ad[r * NH + hA] = da;
                            g_as[r * NH + hB] = sb;
                            g_ad[r * NH + hB] = db;
                        }
                    }
                }
            }
        }
    }
}

// ---------------- CSR build ----------------
__global__ void zero_cnt_kernel() {
    int i = blockIdx.x * blockDim.x + threadIdx.x;
    if (i < NN) g_cnt[i] = 0;
    if (i == 0) g_total = 0;
}

__global__ void hist_kernel(const int* __restrict__ dst) {
    int e = blockIdx.x * blockDim.x + threadIdx.x;
    if (e < NE) atomicAdd(&g_cnt[dst[e]], 1);
}

__global__ void alloc_kernel() {
    int i = blockIdx.x * blockDim.x + threadIdx.x;
    if (i >= NN) return;
    int c = g_cnt[i];
    int r = atomicAdd(&g_total, c);
    g_rowptr[i] = r;
    g_cursor[i] = r;
}

__global__ void scatter_kernel(const int* __restrict__ src,
                               const int* __restrict__ dst) {
    int e = blockIdx.x * blockDim.x + threadIdx.x;
    if (e >= NE) return;
    int d = dst[e];
    int pos = atomicAdd(&g_cursor[d], 1);
    g_csr_src[pos] = src[e];
}

// ---------------- node aggregation: half-warp per edge, 2-wide, single pass ----------------
__global__ void __launch_bounds__(256)
node_agg_kernel(float* __restrict__ out)
{
    int d = (blockIdx.x * blockDim.x + threadIdx.x) >> 5;
    int lane = threadIdx.x & 31;
    if (d >= NN) return;
    const int n = g_cnt[d];
    if (n == 0) return;   // out already holds the residual
    const int base = g_rowptr[d];

    const int half = lane >> 4;
    const int l16  = lane & 15;
    const int h    = l16 >> 2;
    const float adh = g_ad[(size_t)d * NH + h];

    float acc[8];
#pragma unroll
    for (int q = 0; q < 8; q++) acc[q] = 0.f;
    float den = 0.f;

    const int* cs = g_csr_src + base;
    const __half* xb = g_xh + (size_t)l16 * 8;

    int i = half;
    for (; i + 2 < n; i += 4) {
        int s0 = cs[i], s1 = cs[i + 2];
        float a0 = g_as[(size_t)s0 * NH + h];
        float a1 = g_as[(size_t)s1 * NH + h];
        uint4 v0 = *(const uint4*)(xb + (size_t)s0 * 128);
        uint4 v1 = *(const uint4*)(xb + (size_t)s1 * 128);
        float p0 = __expf(lrelu(a0 + adh));
        float p1 = __expf(lrelu(a1 + adh));
        den += p0 + p1;
        const __half2* b0 = (const __half2*)&v0;
        const __half2* b1 = (const __half2*)&v1;
#pragma unroll
        for (int q = 0; q < 4; q++) {
            float2 f0 = __half22float2(b0[q]);
            float2 f1 = __half22float2(b1[q]);
            acc[2 * q]     = fmaf(f0.x, p0, acc[2 * q]);
            acc[2 * q + 1] = fmaf(f0.y, p0, acc[2 * q + 1]);
            acc[2 * q]     = fmaf(f1.x, p1, acc[2 * q]);
            acc[2 * q + 1] = fmaf(f1.y, p1, acc[2 * q + 1]);
        }
    }
    if (i < n) {
        int s0 = cs[i];
        float a0 = g_as[(size_t)s0 * NH + h];
        uint4 v0 = *(const uint4*)(xb + (size_t)s0 * 128);
        float p0 = __expf(lrelu(a0 + adh));
        den += p0;
        const __half2* b0 = (const __half2*)&v0;
#pragma unroll
        for (int q = 0; q < 4; q++) {
            float2 f0 = __half22float2(b0[q]);
            acc[2 * q]     = fmaf(f0.x, p0, acc[2 * q]);
            acc[2 * q + 1] = fmaf(f0.y, p0, acc[2 * q + 1]);
        }
    }

#pragma unroll
    for (int q = 0; q < 8; q++)
        acc[q] += __shfl_xor_sync(0xffffffffu, acc[q], 16);
    den += __shfl_xor_sync(0xffffffffu, den, 16);

    if (half == 0) {
        const float inv = 1.0f / den;
        float* o = out + (size_t)d * 128 + l16 * 8;
        float4 r0 = *(const float4*)o;
        float4 r1 = *(const float4*)(o + 4);
        r0.x = fmaf(acc[0], inv, r0.x);
        r0.y = fmaf(acc[1], inv, r0.y);
        r0.z = fmaf(acc[2], inv, r0.z);
        r0.w = fmaf(acc[3], inv, r0.w);
        r1.x = fmaf(acc[4], inv, r1.x);
        r1.y = fmaf(acc[5], inv, r1.y);
        r1.z = fmaf(acc[6], inv, r1.z);
        r1.w = fmaf(acc[7], inv, r1.w);
        *(float4*)o = r0;
        *(float4*)(o + 4) = r1;
    }
}

// ---------------- launch ----------------
extern "C" void kernel_launch(void* const* d_in, const int* in_sizes, int n_in,
                              void* d_out, int out_size)
{
    const float* feat    = (const float*)d_in[0];
    const float* W       = (const float*)d_in[1];
    const float* att_src = (const float*)d_in[2];
    const float* att_dst = (const float*)d_in[3];
    const float* Wres    = (const float*)d_in[4];
    const int*   src     = (const int*)d_in[5];
    const int*   dst     = (const int*)d_in[6];
    float* out = (float*)d_out;

    static cudaStream_t s2 = nullptr;
    static cudaEvent_t evFork = nullptr, evJoin = nullptr;
    if (!s2) {
        cudaFuncSetAttribute(gemm_tc,
                             cudaFuncAttributeMaxDynamicSharedMemorySize,
                             GEMM_SMEM);
        cudaStreamCreateWithFlags(&s2, cudaStreamNonBlocking);
        cudaEventCreateWithFlags(&evFork, cudaEventDisableTiming);
        cudaEventCreateWithFlags(&evJoin, cudaEventDisableTiming);
    }

    // fork: CSR build on s2, prep+GEMM on the main stream.
    // Enqueue order keeps gemm_tc 4th (profiler targeting).
    cudaEventRecord(evFork, 0);
    cudaStreamWaitEvent(s2, evFork, 0);

    zero_cnt_kernel<<<NB, 256, 0, s2>>>();                       // 1
    hist_kernel<<<(NE + 255) / 256, 256, 0, s2>>>(dst);          // 2
    prep_ab<<<16 + (NN * 16 + 255) / 256, 256>>>(W, Wres, feat); // 3
    gemm_tc<<<NCTA, 512, GEMM_SMEM>>>(att_src, att_dst, out);    // 4
    alloc_kernel<<<NB, 256, 0, s2>>>();                          // 5
    scatter_kernel<<<(NE + 255) / 256, 256, 0, s2>>>(src, dst);  // 6
    cudaEventRecord(evJoin, s2);

    // join: aggregation needs both GEMM outputs and the CSR
    cudaStreamWaitEvent(0, evJoin, 0);
    node_agg_kernel<<<(NN * 32 + 255) / 256, 256>>>(out);        // 7
}